// round 14
// baseline (speedup 1.0000x reference)
#include <cuda_runtime.h>
#include <cuda_fp16.h>
#include <cstdint>

#define BATCH 4096
#define SEQ   24
#define TT    32
#define VOC   120
#define EMB   128
#define HE    512
#define HD    512
#define START_TOKEN 2
#define NG    2048   // interleaved gates
#define PGRID 296    // persistent grid: 2 CTAs/SM * 148 SMs

typedef __half fp16;
typedef unsigned int u32;

// ---------------- device scratch ----------------
__device__ __align__(256) fp16 g_ench[(size_t)BATCH * SEQ * HE];
__device__ __align__(256) fp16 g_ef[(size_t)BATCH * HE];
__device__ __align__(256) float g_encproj[(size_t)BATCH * SEQ * HD];
__device__ __align__(256) float g_ctxw[(size_t)BATCH * SEQ * HD];
__device__ __align__(256) float g_encw[(size_t)BATCH * SEQ];
__device__ __align__(256) float g_embproj[(size_t)VOC * 4 * HD];   // [tok][4d+g]
// weights (single fp16)
__device__ __align__(256) fp16 g_wg[(size_t)NG * HD];              // W_hh interleaved
__device__ __align__(256) fp16 g_wqa[(size_t)1024 * HD];           // [W_dec^T ; W_ap1]
__device__ __align__(256) float g_bqa[1024];
__device__ __align__(256) fp16 g_we[(size_t)HE * HD];
__device__ __align__(256) fp16 g_wapc[(size_t)HD * HE];
__device__ __align__(256) fp16 g_woc[(size_t)121 * HD];
__device__ __align__(256) float g_boc[121];
__device__ __align__(256) fp16 g_wi[(size_t)HD * HE];
// activations (single fp16)
__device__ __align__(256) fp16 g_h_all[(size_t)(TT + 1) * BATCH * HD];
__device__ __align__(256) float g_c[(size_t)BATCH * HD];
__device__ __align__(256) float g_qa[(size_t)TT * BATCH * 1024];   // [q | ahp2]
__device__ __align__(256) fp16 g_ah_all[(size_t)TT * BATCH * HD];
__device__ __align__(256) float g_logits_all[(size_t)TT * BATCH * 121];
__device__ __align__(256) float g_ctxdot[(size_t)TT * BATCH];
__device__ u32 g_bar;   // persistent-kernel grid barrier (reset by prep_all)

// ---------------- math helpers ----------------
__device__ __forceinline__ float tanh_fast(float x) {
    float e = __expf(2.0f * x);
    return 1.0f - __fdividef(2.0f, e + 1.0f);
}
__device__ __forceinline__ float sigmoid_fast(float x) {
    return __fdividef(1.0f, 1.0f + __expf(-x));
}

// ---------------- PTX helpers ----------------
__device__ __forceinline__ u32 smem_u32(const void* p) {
    u32 a;
    asm("{ .reg .u64 t; cvta.to.shared.u64 t, %1; cvt.u32.u64 %0, t; }"
        : "=r"(a) : "l"(p));
    return a;
}
__device__ __forceinline__ void cp16(u32 d, const void* s, u32 sz) {
    asm volatile("cp.async.cg.shared.global [%0], [%1], 16, %2;"
                 :: "r"(d), "l"(s), "r"(sz) : "memory");
}
__device__ __forceinline__ void cp_commit() {
    asm volatile("cp.async.commit_group;" ::: "memory");
}
template<int N>
__device__ __forceinline__ void cp_wait() {
    asm volatile("cp.async.wait_group %0;" :: "n"(N) : "memory");
}
__device__ __forceinline__ void ldsm_x4(u32* r, u32 a) {
    asm volatile("ldmatrix.sync.aligned.m8n8.x4.shared.b16 {%0,%1,%2,%3}, [%4];"
                 : "=r"(r[0]), "=r"(r[1]), "=r"(r[2]), "=r"(r[3]) : "r"(a));
}
__device__ __forceinline__ void mma_f16(float* c, const u32* a, const u32* b) {
    asm volatile(
        "mma.sync.aligned.m16n8k16.row.col.f32.f16.f16.f32 "
        "{%0,%1,%2,%3}, {%4,%5,%6,%7}, {%8,%9}, {%0,%1,%2,%3};"
        : "+f"(c[0]), "+f"(c[1]), "+f"(c[2]), "+f"(c[3])
        : "r"(a[0]), "r"(a[1]), "r"(a[2]), "r"(a[3]), "r"(b[0]), "r"(b[1]));
}

// ======== GEMM mainloop (blockIdx-based kernels): A fp16, B fp16 ========
// per-buffer: A@0 (10240 B) B@10240 (BN*80 B); row stride 80 B.
#define GEMM_MAINLOOP(BN, NTN, LDA, LDB, NREAL)                                 \
    constexpr int BUFB = 10240 + (BN) * 80;                                     \
    extern __shared__ char smem[];                                              \
    const u32 sb = smem_u32(smem);                                              \
    const int tid = threadIdx.x, lane = tid & 31, wid = tid >> 5;               \
    const int bm = blockIdx.y * 128, bn = blockIdx.x * (BN);                    \
    const int wm = (wid >> 1) * 32, wn = (wid & 1) * ((BN) / 2);                \
    float acc[2][NTN][4];                                                       \
    _Pragma("unroll") for (int m = 0; m < 2; m++)                               \
    _Pragma("unroll") for (int n = 0; n < NTN; n++)                             \
    _Pragma("unroll") for (int j = 0; j < 4; j++) acc[m][n][j] = 0.0f;          \
    const int nch = K / 32;                                                     \
    auto stage = [&](int c) {                                                   \
        const int kt = c * 32;                                                  \
        const u32 bufb = sb + (u32)(c & 1) * BUFB;                              \
        _Pragma("unroll") for (int p = 0; p < 2; p++) {                         \
            int v = tid + p * 256, row = v >> 2, g = v & 3;                     \
            size_t go = (size_t)(bm + row) * (LDA) + kt + g * 8;                \
            cp16(bufb + row * 80 + g * 16, Aw + go, 16);                        \
        }                                                                       \
        _Pragma("unroll") for (int p = 0; p < (BN) / 64; p++) {                 \
            int v = tid + p * 256, row = v >> 2, g = v & 3;                     \
            int n = bn + row;                                                   \
            int na = (n < (NREAL)) ? n : ((NREAL) - 1);                         \
            u32 sz = (n < (NREAL)) ? 16u : 0u;                                  \
            size_t go = (size_t)na * (LDB) + kt + g * 8;                        \
            cp16(bufb + 10240 + row * 80 + g * 16, Bw + go, sz);                \
        }                                                                       \
    };                                                                          \
    stage(0);                                                                   \
    cp_commit();                                                                \
    for (int c = 0; c < nch; c++) {                                             \
        if (c + 1 < nch) { stage(c + 1); cp_commit(); cp_wait<1>(); }           \
        else             { cp_wait<0>(); }                                      \
        __syncthreads();                                                        \
        const u32 bufb = sb + (u32)(c & 1) * BUFB;                              \
        _Pragma("unroll") for (int k2 = 0; k2 < 2; k2++) {                      \
            const u32 kb = k2 * 32;                                             \
            const u32 a0 = bufb + (wm + (lane & 15)) * 80 + kb + (lane >> 4) * 16; \
            u32 ahf[2][4];                                                      \
            ldsm_x4(ahf[0], a0); ldsm_x4(ahf[1], a0 + 16 * 80);                 \
            const u32 bb0 = bufb + 10240 +                                      \
                (wn + (lane & 7) + ((lane >> 4) & 1) * 8) * 80 +                \
                kb + ((lane >> 3) & 1) * 16;                                    \
            _Pragma("unroll") for (int nt2 = 0; nt2 < (NTN) / 2; nt2++) {       \
                u32 bh4[4];                                                     \
                ldsm_x4(bh4, bb0 + nt2 * 16 * 80);                              \
                _Pragma("unroll") for (int half = 0; half < 2; half++) {        \
                    int nt = nt2 * 2 + half;                                    \
                    const u32* bhf = bh4 + half * 2;                            \
                    _Pragma("unroll") for (int m = 0; m < 2; m++)               \
                        mma_f16(acc[m][nt], ahf[m], bhf);                       \
                }                                                               \
            }                                                                   \
        }                                                                       \
        __syncthreads();                                                        \
    }

// ---------------- generic GEMM ----------------
template<int BN, bool HALFOUT>
__global__ __launch_bounds__(256, 2)
void mma_gemm_k(const fp16* __restrict__ Aw, int lda,
                const fp16* __restrict__ Bw, int ldb,
                const float* __restrict__ bias,
                float* __restrict__ C, fp16* __restrict__ Ch,
                int K, int Nreal)
{
    GEMM_MAINLOOP(BN, BN / 16, lda, ldb, Nreal)

    auto emit = [&](int r, int n, float v) {
        if (n >= Nreal) return;
        size_t o = (size_t)r * Nreal + n;
        if (bias) v += bias[n];
        if (C) C[o] = v;
        if (HALFOUT) Ch[o] = __float2half(v);
    };
#pragma unroll
    for (int m = 0; m < 2; m++) {
        int r0 = bm + wm + m * 16 + (lane >> 2);
#pragma unroll
        for (int nt = 0; nt < BN / 16; nt++) {
            int gn = bn + wn + nt * 8 + (lane & 3) * 2;
            emit(r0,     gn,     acc[m][nt][0]);
            emit(r0,     gn + 1, acc[m][nt][1]);
            emit(r0 + 8, gn,     acc[m][nt][2]);
            emit(r0 + 8, gn + 1, acc[m][nt][3]);
        }
    }
}

// ---------------- persistent tile: BN=64 gates GEMM + LSTM cell ----------------
// smem per CTA: 2 * (10240 + 64*80) = 30720 bytes.
#define PBUFB 15360
__device__ __forceinline__ void cell_tile64(
    const fp16* __restrict__ Aw, const fp16* __restrict__ Bw,
    const float* __restrict__ ep, const int* __restrict__ tgt,
    float* __restrict__ cst, fp16* __restrict__ hout,
    int tok_step, int bm, int bn, u32 sb)
{
    const int tid = threadIdx.x, lane = tid & 31, wid = tid >> 5;
    const int wm = (wid >> 1) * 32, wn = (wid & 1) * 32;
    float acc[2][4][4];
#pragma unroll
    for (int m = 0; m < 2; m++)
#pragma unroll
        for (int n = 0; n < 4; n++)
#pragma unroll
            for (int j = 0; j < 4; j++) acc[m][n][j] = 0.0f;

    auto stage = [&](int c) {
        const int kt = c * 32;
        const u32 bufb = sb + (u32)(c & 1) * PBUFB;
#pragma unroll
        for (int p = 0; p < 2; p++) {
            int v = tid + p * 256, row = v >> 2, g = v & 3;
            size_t go = (size_t)(bm + row) * HD + kt + g * 8;
            cp16(bufb + row * 80 + g * 16, Aw + go, 16);
        }
        {
            int row = tid >> 2, g = tid & 3;
            size_t go = (size_t)(bn + row) * HD + kt + g * 8;
            cp16(bufb + 10240 + row * 80 + g * 16, Bw + go, 16);
        }
    };

    stage(0);
    cp_commit();
    for (int c = 0; c < 16; c++) {
        if (c + 1 < 16) { stage(c + 1); cp_commit(); cp_wait<1>(); }
        else            { cp_wait<0>(); }
        __syncthreads();
        const u32 bufb = sb + (u32)(c & 1) * PBUFB;
#pragma unroll
        for (int k2 = 0; k2 < 2; k2++) {
            const u32 kb = k2 * 32;
            const u32 a0 = bufb + (wm + (lane & 15)) * 80 + kb + (lane >> 4) * 16;
            u32 ahf[2][4];
            ldsm_x4(ahf[0], a0); ldsm_x4(ahf[1], a0 + 16 * 80);
            const u32 bb0 = bufb + 10240 +
                (wn + (lane & 7) + ((lane >> 4) & 1) * 8) * 80 +
                kb + ((lane >> 3) & 1) * 16;
#pragma unroll
            for (int nt2 = 0; nt2 < 2; nt2++) {
                u32 bh4[4];
                ldsm_x4(bh4, bb0 + nt2 * 16 * 80);
#pragma unroll
                for (int half = 0; half < 2; half++) {
                    int nt = nt2 * 2 + half;
                    const u32* bhf = bh4 + half * 2;
#pragma unroll
                    for (int m = 0; m < 2; m++)
                        mma_f16(acc[m][nt], ahf[m], bhf);
                }
            }
        }
        __syncthreads();
    }

#pragma unroll
    for (int m = 0; m < 2; m++) {
        int r0 = bm + wm + m * 16 + (lane >> 2);
        int r1 = r0 + 8;
        int tok0 = (tok_step == 0) ? START_TOKEN : tgt[(size_t)r0 * TT + tok_step - 1];
        int tok1 = (tok_step == 0) ? START_TOKEN : tgt[(size_t)r1 * TT + tok_step - 1];
        const float* e0 = ep + (size_t)tok0 * 4 * HD;
        const float* e1 = ep + (size_t)tok1 * 4 * HD;
#pragma unroll
        for (int nt = 0; nt < 4; nt++) {
            int gn = bn + wn + nt * 8 + (lane & 3) * 2;
            float v0 = acc[m][nt][0] + e0[gn];
            float v1 = acc[m][nt][1] + e0[gn + 1];
            float v2 = acc[m][nt][2] + e1[gn];
            float v3 = acc[m][nt][3] + e1[gn + 1];
            float p0 = __shfl_xor_sync(0xffffffffu, v0, 1);
            float p1 = __shfl_xor_sync(0xffffffffu, v1, 1);
            float p2 = __shfl_xor_sync(0xffffffffu, v2, 1);
            float p3 = __shfl_xor_sync(0xffffffffu, v3, 1);
            if (!(lane & 1)) {
                int d = gn >> 2;
                {
                    size_t ci = (size_t)r0 * HD + d;
                    float cn = sigmoid_fast(v1) * cst[ci]
                             + sigmoid_fast(v0) * tanh_fast(p0);
                    cst[ci] = cn;
                    hout[ci] = __float2half(sigmoid_fast(p1) * tanh_fast(cn));
                }
                {
                    size_t ci = (size_t)r1 * HD + d;
                    float cn = sigmoid_fast(v3) * cst[ci]
                             + sigmoid_fast(v2) * tanh_fast(p2);
                    cst[ci] = cn;
                    hout[ci] = __float2half(sigmoid_fast(p3) * tanh_fast(cn));
                }
            }
        }
    }
}

// persistent kernel: all TT steps in one launch with grid barrier
__global__ __launch_bounds__(256, 2)
void loop_cell_pk(const fp16* __restrict__ wg,
                  const float* __restrict__ ep,
                  const int* __restrict__ tgt,
                  float* __restrict__ cst,
                  fp16* __restrict__ h_all)
{
    extern __shared__ char smem[];
    const u32 sb = smem_u32(smem);
    for (int t = 0; t < TT; t++) {
        const fp16* Aw = h_all + (size_t)t * BATCH * HD;
        fp16* hout = h_all + (size_t)(t + 1) * BATCH * HD;
        for (int idx = blockIdx.x; idx < 1024; idx += gridDim.x)
            cell_tile64(Aw, wg, ep, tgt, cst, hout, t,
                        (idx >> 5) * 128, (idx & 31) * 64, sb);
        // grid barrier: release h writes, arrive, spin, acquire
        __syncthreads();
        __threadfence();
        if (threadIdx.x == 0) {
            atomicAdd(&g_bar, 1u);
            u32 target = gridDim.x * (u32)(t + 1);
            while (atomicAdd(&g_bar, 0u) < target) __nanosleep(64);
        }
        __syncthreads();
        __threadfence();
    }
}

// ---------------- merged weight prep (one launch; also resets barrier) ----------------
#define R0 ((size_t)NG * HD)
#define R1 (R0 + (size_t)1024 * HD)
#define R2 (R1 + (size_t)HE * HD)
#define R3 (R2 + (size_t)HD * HE)
#define R4 (R3 + (size_t)121 * HD)
#define R5 (R4 + (size_t)HD * HE)
#define R6 (R5 + (size_t)BATCH * HD)
__global__ void prep_all_k(const float* __restrict__ W_hh,
                           const float* __restrict__ W_dec,
                           const float* __restrict__ W_ap,
                           const float* __restrict__ b_attn,
                           const float* __restrict__ W_enc_attn,
                           const float* __restrict__ W_out,
                           const float* __restrict__ b_out,
                           const float* __restrict__ w_copy,
                           const float* __restrict__ b_copy,
                           const float* __restrict__ W_init,
                           fp16* __restrict__ wg, fp16* __restrict__ wqa,
                           float* __restrict__ bqa,
                           fp16* __restrict__ we, fp16* __restrict__ wapc,
                           fp16* __restrict__ woc, float* __restrict__ boc,
                           fp16* __restrict__ wi, float* __restrict__ cst)
{
    if (blockIdx.x == 0 && threadIdx.x == 0) g_bar = 0u;
    for (size_t i = (size_t)blockIdx.x * blockDim.x + threadIdx.x; i < R6;
         i += (size_t)gridDim.x * blockDim.x) {
        if (i < R0) {
            int row = (int)(i / HD), k = (int)(i % HD);
            int src = (row & 3) * HD + (row >> 2);
            wg[i] = __float2half(W_hh[(size_t)src * HD + k]);
        } else if (i < R1) {
            size_t j = i - R0;
            int row = (int)(j / HD), k = (int)(j % HD);
            float v = (row < 512) ? W_dec[(size_t)k * HD + row]
                                  : W_ap[(size_t)(row - 512) * (HD + HE) + k];
            wqa[j] = __float2half(v);
            if (j < 1024) bqa[j] = (j < 512) ? b_attn[j] : 0.0f;
        } else if (i < R2) {
            size_t j = i - R1;
            int n = (int)(j / HE), k = (int)(j % HE);
            we[j] = __float2half(W_enc_attn[(size_t)k * HD + n]);
        } else if (i < R3) {
            size_t j = i - R2;
            int row = (int)(j / HE), k = (int)(j % HE);
            wapc[j] = __float2half(W_ap[(size_t)row * (HD + HE) + HD + k]);
        } else if (i < R4) {
            size_t j = i - R3;
            int row = (int)(j / HD), k = (int)(j % HD);
            float v = (row < VOC) ? W_out[(size_t)row * HD + k] : w_copy[k];
            woc[j] = __float2half(v);
            if (j < 121) boc[j] = (j < VOC) ? b_out[j] : b_copy[0];
        } else if (i < R5) {
            size_t j = i - R4;
            wi[j] = __float2half(W_init[j]);
        } else {
            cst[i - R5] = 0.0f;
        }
    }
}

__global__ void conv_h_k(const float* __restrict__ src, fp16* __restrict__ dst, size_t n)
{
    for (size_t i = (size_t)blockIdx.x * blockDim.x + threadIdx.x; i < n;
         i += (size_t)gridDim.x * blockDim.x)
        dst[i] = __float2half(src[i]);
}

__global__ void embproj_k(const float* __restrict__ embed,
                          const float* __restrict__ W_ih,
                          const float* __restrict__ b_ih,
                          const float* __restrict__ b_hh,
                          float* __restrict__ ep)
{
    int v = blockIdx.y;
    int n = blockIdx.x * 128 + threadIdx.x;
    int j = (n & 3) * HD + (n >> 2);
    __shared__ float em[EMB];
    if (threadIdx.x < EMB) em[threadIdx.x] = embed[(size_t)v * EMB + threadIdx.x];
    __syncthreads();
    float acc = b_ih[j] + b_hh[j];
    const float* w = W_ih + (size_t)j * EMB;
#pragma unroll 8
    for (int k = 0; k < EMB; k++) acc += em[k] * w[k];
    ep[(size_t)v * 4 * HD + n] = acc;
}

// warp per row, grid-stride
__global__ void encw_k(const float* __restrict__ enc,
                       const float* __restrict__ w_copy,
                       float* __restrict__ encw)
{
    __shared__ __align__(16) float wsh[HE];
    for (int k = threadIdx.x; k < HE; k += blockDim.x) wsh[k] = w_copy[HD + k];
    __syncthreads();
    int lane = threadIdx.x & 31;
    int gw = (blockIdx.x * blockDim.x + threadIdx.x) >> 5;
    int nw = (gridDim.x * blockDim.x) >> 5;
    for (int r = gw; r < BATCH * SEQ; r += nw) {
        const float4* row = (const float4*)(enc + (size_t)r * HE);
        float acc = 0.f;
#pragma unroll
        for (int j = 0; j < 4; j++) {
            int d4 = lane + j * 32;
            float4 v = row[d4];
            float4 w = *(const float4*)&wsh[d4 * 4];
            acc += v.x * w.x + v.y * w.y + v.z * w.z + v.w * w.w;
        }
#pragma unroll
        for (int o = 16; o; o >>= 1) acc += __shfl_xor_sync(0xffffffffu, acc, o);
        if (lane == 0) encw[r] = acc;
    }
}

// ---------------- merged attention + ctx pass: block per b ----------------
#define AC_SMEM ((SEQ * HD + 4 * HD + TT * SEQ + 4 * SEQ) * 4)
__global__ __launch_bounds__(256)
void attnctx_k(const float* __restrict__ encproj,
               const float* __restrict__ ctxw,
               const float* __restrict__ encw,
               const float* __restrict__ qa,
               const float* __restrict__ v_attn,
               const float* __restrict__ b_ap,
               float* __restrict__ attn_out,
               fp16* __restrict__ ah,
               float* __restrict__ ctxdot)
{
    int b = blockIdx.x;
    int tid = threadIdx.x;
    extern __shared__ float sm[];
    float* buf = sm;
    float* qs  = sm + SEQ * HD;
    float* ap  = qs + 4 * HD;
    float* sc  = ap + TT * SEQ;
    __shared__ __align__(16) float vsh[HD];
    __shared__ float ew[SEQ];

    {
        const float4* src = (const float4*)(encproj + (size_t)b * SEQ * HD);
        float4* dst = (float4*)buf;
        for (int i = tid; i < SEQ * HD / 4; i += 256) dst[i] = src[i];
    }
    for (int d = tid; d < HD; d += 256) vsh[d] = v_attn[d];
    if (tid < SEQ) ew[tid] = encw[(size_t)b * SEQ + tid];
    __syncthreads();

    int w = tid >> 5, lane = tid & 31;
    for (int tc = 0; tc < TT; tc += 4) {
        for (int i = tid; i < 4 * HD / 4; i += 256) {
            int t = i / (HD / 4), dd = i % (HD / 4);
            ((float4*)qs)[i] =
                ((const float4*)(qa + ((size_t)(tc + t) * BATCH + b) * 1024))[dd];
        }
        __syncthreads();

        for (int task = w; task < 4 * SEQ; task += 8) {
            int t = task / SEQ, s = task % SEQ;
            const float4* row4 = (const float4*)(buf + s * HD);
            const float4* q4p = (const float4*)(qs + t * HD);
            float acc = 0.f;
#pragma unroll
            for (int j = 0; j < 4; j++) {
                int d4 = lane + j * 32;
                float4 e4 = row4[d4];
                float4 q4 = q4p[d4];
                float4 v4 = *(const float4*)&vsh[d4 * 4];
                acc += tanh_fast(e4.x + q4.x) * v4.x;
                acc += tanh_fast(e4.y + q4.y) * v4.y;
                acc += tanh_fast(e4.z + q4.z) * v4.z;
                acc += tanh_fast(e4.w + q4.w) * v4.w;
            }
#pragma unroll
            for (int o = 16; o; o >>= 1) acc += __shfl_xor_sync(0xffffffffu, acc, o);
            if (lane == 0) sc[t * SEQ + s] = acc;
        }
        __syncthreads();

        if (w < 4) {
            float e = (lane < SEQ) ? __expf(sc[w * SEQ + lane]) : 0.f;
            float sum = e;
#pragma unroll
            for (int o = 16; o; o >>= 1) sum += __shfl_xor_sync(0xffffffffu, sum, o);
            if (lane < SEQ) {
                float a = __fdividef(e, sum);
                ap[(tc + w) * SEQ + lane] = a;
                attn_out[(size_t)b * TT * SEQ + (size_t)(tc + w) * SEQ + lane] = a;
            }
        }
        __syncthreads();
    }

    if (tid < TT) {
        float cd = 0.f;
#pragma unroll
        for (int s = 0; s < SEQ; s++) cd += ap[tid * SEQ + s] * ew[s];
        ctxdot[(size_t)tid * BATCH + b] = cd;
    }
    {
        const float4* src = (const float4*)(ctxw + (size_t)b * SEQ * HD);
        float4* dst = (float4*)buf;
        for (int i = tid; i < SEQ * HD / 4; i += 256) dst[i] = src[i];
    }
    __syncthreads();

    float bap0 = b_ap[tid], bap1 = b_ap[tid + 256];
    for (int t = 0; t < TT; t++) {
        float a0 = 0.f, a1 = 0.f;
        const float* apt = ap + t * SEQ;
#pragma unroll
        for (int s = 0; s < SEQ; s++) {
            float a = apt[s];
            a0 += a * buf[s * HD + tid];
            a1 += a * buf[s * HD + tid + 256];
        }
        const float* qrow = qa + ((size_t)t * BATCH + b) * 1024 + 512;
        size_t base = (size_t)t * BATCH * HD + (size_t)b * HD;
        ah[base + tid]       = __float2half(tanh_fast(qrow[tid] + a0 + bap0));
        ah[base + tid + 256] = __float2half(tanh_fast(qrow[tid + 256] + a1 + bap1));
    }
}

// ---------------- output mix: warp per (t,b) row ----------------
__global__ void out2_k(const float* __restrict__ logits_all,
                       const float* __restrict__ ctxdot,
                       const int* __restrict__ input_char_ids,
                       const float* __restrict__ attn_base,
                       float* __restrict__ outputs)
{
    int warp = threadIdx.x >> 5, lane = threadIdx.x & 31;
    int row = blockIdx.x * 4 + warp;
    int t = row >> 12;
    int b = row & 4095;
    __shared__ float cbuf[4][VOC];

    for (int k = lane; k < VOC; k += 32) cbuf[warp][k] = 0.f;
    __syncwarp();
    if (lane < SEQ) {
        int id = input_char_ids[(size_t)b * SEQ + lane];
        float a = attn_base[(size_t)b * TT * SEQ + (size_t)t * SEQ + lane];
        atomicAdd(&cbuf[warp][id], a);
    }
    __syncwarp();

    const float* lrow = logits_all + (size_t)row * 121;
    float p = sigmoid_fast(lrow[120] + ctxdot[row]);

    float e[4];
    float sum = 0.f;
#pragma unroll
    for (int j = 0; j < 4; j++) {
        int idx = lane + j * 32;
        e[j] = (idx < VOC) ? __expf(lrow[idx]) : 0.f;
        sum += e[j];
    }
#pragma unroll
    for (int o = 16; o; o >>= 1) sum += __shfl_xor_sync(0xffffffffu, sum, o);
    float inv = __fdividef(1.0f - p, sum);
#pragma unroll
    for (int j = 0; j < 4; j++) {
        int idx = lane + j * 32;
        if (idx < VOC)
            outputs[(size_t)b * TT * VOC + (size_t)t * VOC + idx] =
                inv * e[j] + p * cbuf[warp][idx];
    }
}

// ---------------- host ----------------
#define SYM(p, s) cudaGetSymbolAddress((void**)&(p), s)
#define SM128 40960
#define SM64  30720

extern "C" void kernel_launch(void* const* d_in, const int* in_sizes, int n_in,
                              void* d_out, int out_size)
{
    (void)in_sizes; (void)n_in; (void)out_size;
    const float* enc        = (const float*)d_in[0];
    const float* enc_final  = (const float*)d_in[1];
    const int*   tgt        = (const int*)d_in[2];
    const int*   input_ids  = (const int*)d_in[3];
    const float* embed      = (const float*)d_in[4];
    const float* W_init     = (const float*)d_in[5];
    const float* b_init     = (const float*)d_in[6];
    const float* W_ih       = (const float*)d_in[7];
    const float* W_hh       = (const float*)d_in[8];
    const float* b_ih       = (const float*)d_in[9];
    const float* b_hh       = (const float*)d_in[10];
    const float* W_enc_attn = (const float*)d_in[11];
    const float* W_dec_attn = (const float*)d_in[12];
    const float* b_attn     = (const float*)d_in[13];
    const float* v_attn     = (const float*)d_in[14];
    const float* W_ap       = (const float*)d_in[15];
    const float* b_ap       = (const float*)d_in[16];
    const float* W_out      = (const float*)d_in[17];
    const float* b_out      = (const float*)d_in[18];
    const float* w_copy     = (const float*)d_in[19];
    const float* b_copy     = (const float*)d_in[20];

    float* out = (float*)d_out;
    float* outputs   = out;
    float* attn_base = out + (size_t)BATCH * TT * VOC;

    fp16 *ench, *ef, *wg, *wqa, *we, *wapc, *woc, *wi, *h_all, *ah_all;
    float *encproj, *ctxwp, *encw, *embproj, *bqa, *boc, *cst;
    float *qa, *logits_all, *ctxdot;
    SYM(ench, g_ench); SYM(ef, g_ef);
    SYM(encproj, g_encproj); SYM(ctxwp, g_ctxw); SYM(encw, g_encw);
    SYM(embproj, g_embproj);
    SYM(wg, g_wg);     SYM(wqa, g_wqa); SYM(bqa, g_bqa);
    SYM(we, g_we);     SYM(wapc, g_wapc);
    SYM(woc, g_woc);   SYM(boc, g_boc);
    SYM(wi, g_wi);
    SYM(h_all, g_h_all);
    SYM(cst, g_c);     SYM(qa, g_qa);
    SYM(ah_all, g_ah_all);
    SYM(logits_all, g_logits_all); SYM(ctxdot, g_ctxdot);

    cudaFuncSetAttribute(mma_gemm_k<128, false>,
                         cudaFuncAttributeMaxDynamicSharedMemorySize, SM128);
    cudaFuncSetAttribute(mma_gemm_k<64, true>,
                         cudaFuncAttributeMaxDynamicSharedMemorySize, SM64);
    cudaFuncSetAttribute(loop_cell_pk,
                         cudaFuncAttributeMaxDynamicSharedMemorySize, SM64);
    cudaFuncSetAttribute(attnctx_k,
                         cudaFuncAttributeMaxDynamicSharedMemorySize, AC_SMEM);

    // ---- prep (consolidated; also resets grid barrier) ----
    conv_h_k<<<4096, 256>>>(enc, ench, (size_t)BATCH * SEQ * HE);
    conv_h_k<<<2048, 256>>>(enc_final, ef, (size_t)BATCH * HE);
    embproj_k<<<dim3(16, VOC), 128>>>(embed, W_ih, b_ih, b_hh, embproj);
    prep_all_k<<<1024, 256>>>(W_hh, W_dec_attn, W_ap, b_attn, W_enc_attn,
                              W_out, b_out, w_copy, b_copy, W_init,
                              wg, wqa, bqa, we, wapc, woc, boc, wi, cst);
    encw_k<<<512, 256>>>(enc, w_copy, encw);

    // h_all[0] = enc_final @ W_init^T + b_init
    mma_gemm_k<64, true><<<dim3(8, 32), 256, SM64>>>(
        ef, HE, wi, HE, b_init,
        nullptr, h_all, HE, HD);
    // enc_proj = enc @ W_enc_attn ; ctxw = enc @ W_ap[:,512:]^T
    mma_gemm_k<128, false><<<dim3(4, 768), 256, SM128>>>(
        ench, HE, we, HE, nullptr,
        encproj, nullptr, HE, HD);
    mma_gemm_k<128, false><<<dim3(4, 768), 256, SM128>>>(
        ench, HE, wapc, HE, nullptr,
        ctxwp, nullptr, HE, HD);

    // serial recurrence: ONE persistent kernel for all TT steps
    loop_cell_pk<<<PGRID, 256, SM64>>>(wg, embproj, tgt, cst, h_all);

    // deferred: [q | ahp2] for ALL steps: M = T*B, N = 1024, K = 512
    mma_gemm_k<128, false><<<dim3(8, (TT * BATCH) / 128), 256, SM128>>>(
        h_all + (size_t)BATCH * HD, HD, wqa, HD, bqa,
        qa, nullptr, HD, 1024);

    // merged attention + ctx + ah finalize + ctxdot
    attnctx_k<<<BATCH, 256, AC_SMEM>>>(
        encproj, ctxwp, encw, qa, v_attn, b_ap, attn_base, ah_all, ctxdot);

    // deferred logits+copy GEMM: M = T*B, N = 121, K = 512
    mma_gemm_k<128, false><<<dim3(1, (TT * BATCH) / 128), 256, SM128>>>(
        ah_all, HD, woc, HD, boc,
        logits_all, nullptr, HD, 121);
    out2_k<<<TT * BATCH / 4, 128>>>(logits_all, ctxdot, input_ids, attn_base, outputs);
}

// round 15
// speedup vs baseline: 1.0536x; 1.0536x over previous
#include <cuda_runtime.h>
#include <cuda_fp16.h>
#include <cstdint>

#define BATCH 4096
#define SEQ   24
#define TT    32
#define VOC   120
#define EMB   128
#define HE    512
#define HD    512
#define START_TOKEN 2
#define NG    2048   // interleaved gates

typedef __half fp16;
typedef unsigned int u32;

// ---------------- device scratch ----------------
__device__ __align__(256) fp16 g_ench[(size_t)BATCH * SEQ * HE];
__device__ __align__(256) fp16 g_ef[(size_t)BATCH * HE];
__device__ __align__(256) float g_encproj[(size_t)BATCH * SEQ * HD];
__device__ __align__(256) float g_ctxw[(size_t)BATCH * SEQ * HD];
__device__ __align__(256) float g_encw[(size_t)BATCH * SEQ];
__device__ __align__(256) float g_embproj[(size_t)VOC * 4 * HD];   // [tok][4d+g]
// weights (single fp16)
__device__ __align__(256) fp16 g_wg[(size_t)NG * HD];              // W_hh interleaved
__device__ __align__(256) fp16 g_wqa[(size_t)1024 * HD];           // [W_dec^T ; W_ap1]
__device__ __align__(256) float g_bqa[1024];
__device__ __align__(256) fp16 g_we[(size_t)HE * HD];
__device__ __align__(256) fp16 g_wapc[(size_t)HD * HE];
__device__ __align__(256) fp16 g_woc[(size_t)121 * HD];
__device__ __align__(256) float g_boc[121];
__device__ __align__(256) fp16 g_wi[(size_t)HD * HE];
// activations (single fp16)
__device__ __align__(256) fp16 g_h_all[(size_t)(TT + 1) * BATCH * HD];
__device__ __align__(256) float g_c[(size_t)BATCH * HD];
__device__ __align__(256) float g_qa[(size_t)TT * BATCH * 1024];   // [q | ahp2]
__device__ __align__(256) fp16 g_ah_all[(size_t)TT * BATCH * HD];
__device__ __align__(256) float g_logits_all[(size_t)TT * BATCH * 121];
__device__ __align__(256) float g_ctxdot[(size_t)TT * BATCH];

// ---------------- math helpers ----------------
__device__ __forceinline__ float tanh_fast(float x) {
    float e = __expf(2.0f * x);
    return 1.0f - __fdividef(2.0f, e + 1.0f);
}
__device__ __forceinline__ float sigmoid_fast(float x) {
    return __fdividef(1.0f, 1.0f + __expf(-x));
}

// ---------------- PTX helpers ----------------
__device__ __forceinline__ u32 smem_u32(const void* p) {
    u32 a;
    asm("{ .reg .u64 t; cvta.to.shared.u64 t, %1; cvt.u32.u64 %0, t; }"
        : "=r"(a) : "l"(p));
    return a;
}
__device__ __forceinline__ void cp16(u32 d, const void* s, u32 sz) {
    asm volatile("cp.async.cg.shared.global [%0], [%1], 16, %2;"
                 :: "r"(d), "l"(s), "r"(sz) : "memory");
}
__device__ __forceinline__ void cp_commit() {
    asm volatile("cp.async.commit_group;" ::: "memory");
}
template<int N>
__device__ __forceinline__ void cp_wait() {
    asm volatile("cp.async.wait_group %0;" :: "n"(N) : "memory");
}
__device__ __forceinline__ void ldsm_x4(u32* r, u32 a) {
    asm volatile("ldmatrix.sync.aligned.m8n8.x4.shared.b16 {%0,%1,%2,%3}, [%4];"
                 : "=r"(r[0]), "=r"(r[1]), "=r"(r[2]), "=r"(r[3]) : "r"(a));
}
__device__ __forceinline__ void mma_f16(float* c, const u32* a, const u32* b) {
    asm volatile(
        "mma.sync.aligned.m16n8k16.row.col.f32.f16.f16.f32 "
        "{%0,%1,%2,%3}, {%4,%5,%6,%7}, {%8,%9}, {%0,%1,%2,%3};"
        : "+f"(c[0]), "+f"(c[1]), "+f"(c[2]), "+f"(c[3])
        : "r"(a[0]), "r"(a[1]), "r"(a[2]), "r"(a[3]), "r"(b[0]), "r"(b[1]));
}

// ======== GEMM mainloop: A single fp16, B single fp16 ========
// per-buffer: A@0 (10240 B) B@10240 (BN*80 B); row stride 80 B.
#define GEMM_MAINLOOP(BN, NTN, LDA, LDB, NREAL)                                 \
    constexpr int BUFB = 10240 + (BN) * 80;                                     \
    extern __shared__ char smem[];                                              \
    const u32 sb = smem_u32(smem);                                              \
    const int tid = threadIdx.x, lane = tid & 31, wid = tid >> 5;               \
    const int bm = blockIdx.y * 128, bn = blockIdx.x * (BN);                    \
    const int wm = (wid >> 1) * 32, wn = (wid & 1) * ((BN) / 2);                \
    float acc[2][NTN][4];                                                       \
    _Pragma("unroll") for (int m = 0; m < 2; m++)                               \
    _Pragma("unroll") for (int n = 0; n < NTN; n++)                             \
    _Pragma("unroll") for (int j = 0; j < 4; j++) acc[m][n][j] = 0.0f;          \
    const int nch = K / 32;                                                     \
    auto stage = [&](int c) {                                                   \
        const int kt = c * 32;                                                  \
        const u32 bufb = sb + (u32)(c & 1) * BUFB;                              \
        _Pragma("unroll") for (int p = 0; p < 2; p++) {                         \
            int v = tid + p * 256, row = v >> 2, g = v & 3;                     \
            size_t go = (size_t)(bm + row) * (LDA) + kt + g * 8;                \
            cp16(bufb + row * 80 + g * 16, Aw + go, 16);                        \
        }                                                                       \
        _Pragma("unroll") for (int p = 0; p < (BN) / 64; p++) {                 \
            int v = tid + p * 256, row = v >> 2, g = v & 3;                     \
            int n = bn + row;                                                   \
            int na = (n < (NREAL)) ? n : ((NREAL) - 1);                         \
            u32 sz = (n < (NREAL)) ? 16u : 0u;                                  \
            size_t go = (size_t)na * (LDB) + kt + g * 8;                        \
            cp16(bufb + 10240 + row * 80 + g * 16, Bw + go, sz);                \
        }                                                                       \
    };                                                                          \
    stage(0);                                                                   \
    cp_commit();                                                                \
    for (int c = 0; c < nch; c++) {                                             \
        if (c + 1 < nch) { stage(c + 1); cp_commit(); cp_wait<1>(); }           \
        else             { cp_wait<0>(); }                                      \
        __syncthreads();                                                        \
        const u32 bufb = sb + (u32)(c & 1) * BUFB;                              \
        _Pragma("unroll") for (int k2 = 0; k2 < 2; k2++) {                      \
            const u32 kb = k2 * 32;                                             \
            const u32 a0 = bufb + (wm + (lane & 15)) * 80 + kb + (lane >> 4) * 16; \
            u32 ahf[2][4];                                                      \
            ldsm_x4(ahf[0], a0); ldsm_x4(ahf[1], a0 + 16 * 80);                 \
            const u32 bb0 = bufb + 10240 +                                      \
                (wn + (lane & 7) + ((lane >> 4) & 1) * 8) * 80 +                \
                kb + ((lane >> 3) & 1) * 16;                                    \
            _Pragma("unroll") for (int nt2 = 0; nt2 < (NTN) / 2; nt2++) {       \
                u32 bh4[4];                                                     \
                ldsm_x4(bh4, bb0 + nt2 * 16 * 80);                              \
                _Pragma("unroll") for (int half = 0; half < 2; half++) {        \
                    int nt = nt2 * 2 + half;                                    \
                    const u32* bhf = bh4 + half * 2;                            \
                    _Pragma("unroll") for (int m = 0; m < 2; m++)               \
                        mma_f16(acc[m][nt], ahf[m], bhf);                       \
                }                                                               \
            }                                                                   \
        }                                                                       \
        __syncthreads();                                                        \
    }

// ---------------- generic GEMM ----------------
template<int BN, bool HALFOUT>
__global__ __launch_bounds__(256, 2)
void mma_gemm_k(const fp16* __restrict__ Aw, int lda,
                const fp16* __restrict__ Bw, int ldb,
                const float* __restrict__ bias,
                float* __restrict__ C, fp16* __restrict__ Ch,
                int K, int Nreal)
{
    GEMM_MAINLOOP(BN, BN / 16, lda, ldb, Nreal)

    auto emit = [&](int r, int n, float v) {
        if (n >= Nreal) return;
        size_t o = (size_t)r * Nreal + n;
        if (bias) v += bias[n];
        if (C) C[o] = v;
        if (HALFOUT) Ch[o] = __float2half(v);
    };
#pragma unroll
    for (int m = 0; m < 2; m++) {
        int r0 = bm + wm + m * 16 + (lane >> 2);
#pragma unroll
        for (int nt = 0; nt < BN / 16; nt++) {
            int gn = bn + wn + nt * 8 + (lane & 3) * 2;
            emit(r0,     gn,     acc[m][nt][0]);
            emit(r0,     gn + 1, acc[m][nt][1]);
            emit(r0 + 8, gn,     acc[m][nt][2]);
            emit(r0 + 8, gn + 1, acc[m][nt][3]);
        }
    }
}

// ---------------- fused recurrent gates GEMM + LSTM cell (BN=64) ----------------
// N = 2048 interleaved gates (4d+g, order i,f,g,o); grid (32, 32); 3 CTAs/SM.
__global__ __launch_bounds__(256, 3)
void comb_cell_k(const fp16* __restrict__ Aw,
                 const fp16* __restrict__ Bw,
                 const float* __restrict__ ep,     // [VOC][2048]
                 const int* __restrict__ tgt,
                 float* __restrict__ cst,
                 fp16* __restrict__ hout,
                 int tok_step)
{
    const int K = HD;
    GEMM_MAINLOOP(64, 4, HD, HD, NG)

#pragma unroll
    for (int m = 0; m < 2; m++) {
        int r0 = bm + wm + m * 16 + (lane >> 2);
        int r1 = r0 + 8;
        int tok0 = (tok_step == 0) ? START_TOKEN : tgt[(size_t)r0 * TT + tok_step - 1];
        int tok1 = (tok_step == 0) ? START_TOKEN : tgt[(size_t)r1 * TT + tok_step - 1];
        const float* e0 = ep + (size_t)tok0 * 4 * HD;
        const float* e1 = ep + (size_t)tok1 * 4 * HD;
#pragma unroll
        for (int nt = 0; nt < 4; nt++) {
            int gn = bn + wn + nt * 8 + (lane & 3) * 2;
            float v0 = acc[m][nt][0] + e0[gn];
            float v1 = acc[m][nt][1] + e0[gn + 1];
            float v2 = acc[m][nt][2] + e1[gn];
            float v3 = acc[m][nt][3] + e1[gn + 1];
            float p0 = __shfl_xor_sync(0xffffffffu, v0, 1);
            float p1 = __shfl_xor_sync(0xffffffffu, v1, 1);
            float p2 = __shfl_xor_sync(0xffffffffu, v2, 1);
            float p3 = __shfl_xor_sync(0xffffffffu, v3, 1);
            if (!(lane & 1)) {
                int d = gn >> 2;
                {
                    size_t ci = (size_t)r0 * HD + d;
                    float cn = sigmoid_fast(v1) * cst[ci]
                             + sigmoid_fast(v0) * tanh_fast(p0);
                    cst[ci] = cn;
                    hout[ci] = __float2half(sigmoid_fast(p1) * tanh_fast(cn));
                }
                {
                    size_t ci = (size_t)r1 * HD + d;
                    float cn = sigmoid_fast(v3) * cst[ci]
                             + sigmoid_fast(v2) * tanh_fast(p2);
                    cst[ci] = cn;
                    hout[ci] = __float2half(sigmoid_fast(p3) * tanh_fast(cn));
                }
            }
        }
    }
}

// ---------------- merged weight prep (one launch) ----------------
#define R0 ((size_t)NG * HD)
#define R1 (R0 + (size_t)1024 * HD)
#define R2 (R1 + (size_t)HE * HD)
#define R3 (R2 + (size_t)HD * HE)
#define R4 (R3 + (size_t)121 * HD)
#define R5 (R4 + (size_t)HD * HE)
#define R6 (R5 + (size_t)BATCH * HD)
__global__ void prep_all_k(const float* __restrict__ W_hh,
                           const float* __restrict__ W_dec,
                           const float* __restrict__ W_ap,
                           const float* __restrict__ b_attn,
                           const float* __restrict__ W_enc_attn,
                           const float* __restrict__ W_out,
                           const float* __restrict__ b_out,
                           const float* __restrict__ w_copy,
                           const float* __restrict__ b_copy,
                           const float* __restrict__ W_init,
                           fp16* __restrict__ wg, fp16* __restrict__ wqa,
                           float* __restrict__ bqa,
                           fp16* __restrict__ we, fp16* __restrict__ wapc,
                           fp16* __restrict__ woc, float* __restrict__ boc,
                           fp16* __restrict__ wi, float* __restrict__ cst)
{
    for (size_t i = (size_t)blockIdx.x * blockDim.x + threadIdx.x; i < R6;
         i += (size_t)gridDim.x * blockDim.x) {
        if (i < R0) {
            int row = (int)(i / HD), k = (int)(i % HD);
            int src = (row & 3) * HD + (row >> 2);
            wg[i] = __float2half(W_hh[(size_t)src * HD + k]);
        } else if (i < R1) {
            size_t j = i - R0;
            int row = (int)(j / HD), k = (int)(j % HD);
            float v = (row < 512) ? W_dec[(size_t)k * HD + row]
                                  : W_ap[(size_t)(row - 512) * (HD + HE) + k];
            wqa[j] = __float2half(v);
            if (j < 1024) bqa[j] = (j < 512) ? b_attn[j] : 0.0f;
        } else if (i < R2) {
            size_t j = i - R1;
            int n = (int)(j / HE), k = (int)(j % HE);
            we[j] = __float2half(W_enc_attn[(size_t)k * HD + n]);
        } else if (i < R3) {
            size_t j = i - R2;
            int row = (int)(j / HE), k = (int)(j % HE);
            wapc[j] = __float2half(W_ap[(size_t)row * (HD + HE) + HD + k]);
        } else if (i < R4) {
            size_t j = i - R3;
            int row = (int)(j / HD), k = (int)(j % HD);
            float v = (row < VOC) ? W_out[(size_t)row * HD + k] : w_copy[k];
            woc[j] = __float2half(v);
            if (j < 121) boc[j] = (j < VOC) ? b_out[j] : b_copy[0];
        } else if (i < R5) {
            size_t j = i - R4;
            wi[j] = __float2half(W_init[j]);
        } else {
            cst[i - R5] = 0.0f;
        }
    }
}

__global__ void conv_h_k(const float* __restrict__ src, fp16* __restrict__ dst, size_t n)
{
    for (size_t i = (size_t)blockIdx.x * blockDim.x + threadIdx.x; i < n;
         i += (size_t)gridDim.x * blockDim.x)
        dst[i] = __float2half(src[i]);
}

__global__ void embproj_k(const float* __restrict__ embed,
                          const float* __restrict__ W_ih,
                          const float* __restrict__ b_ih,
                          const float* __restrict__ b_hh,
                          float* __restrict__ ep)
{
    int v = blockIdx.y;
    int n = blockIdx.x * 128 + threadIdx.x;
    int j = (n & 3) * HD + (n >> 2);
    __shared__ float em[EMB];
    if (threadIdx.x < EMB) em[threadIdx.x] = embed[(size_t)v * EMB + threadIdx.x];
    __syncthreads();
    float acc = b_ih[j] + b_hh[j];
    const float* w = W_ih + (size_t)j * EMB;
#pragma unroll 8
    for (int k = 0; k < EMB; k++) acc += em[k] * w[k];
    ep[(size_t)v * 4 * HD + n] = acc;
}

// warp per row, grid-stride
__global__ void encw_k(const float* __restrict__ enc,
                       const float* __restrict__ w_copy,
                       float* __restrict__ encw)
{
    __shared__ __align__(16) float wsh[HE];
    for (int k = threadIdx.x; k < HE; k += blockDim.x) wsh[k] = w_copy[HD + k];
    __syncthreads();
    int lane = threadIdx.x & 31;
    int gw = (blockIdx.x * blockDim.x + threadIdx.x) >> 5;
    int nw = (gridDim.x * blockDim.x) >> 5;
    for (int r = gw; r < BATCH * SEQ; r += nw) {
        const float4* row = (const float4*)(enc + (size_t)r * HE);
        float acc = 0.f;
#pragma unroll
        for (int j = 0; j < 4; j++) {
            int d4 = lane + j * 32;
            float4 v = row[d4];
            float4 w = *(const float4*)&wsh[d4 * 4];
            acc += v.x * w.x + v.y * w.y + v.z * w.z + v.w * w.w;
        }
#pragma unroll
        for (int o = 16; o; o >>= 1) acc += __shfl_xor_sync(0xffffffffu, acc, o);
        if (lane == 0) encw[r] = acc;
    }
}

// ---------------- merged attention + ctx pass: block per b ----------------
#define AC_SMEM ((SEQ * HD + 4 * HD + TT * SEQ + 4 * SEQ) * 4)
__global__ __launch_bounds__(256)
void attnctx_k(const float* __restrict__ encproj,
               const float* __restrict__ ctxw,
               const float* __restrict__ encw,
               const float* __restrict__ qa,
               const float* __restrict__ v_attn,
               const float* __restrict__ b_ap,
               float* __restrict__ attn_out,
               fp16* __restrict__ ah,
               float* __restrict__ ctxdot)
{
    int b = blockIdx.x;
    int tid = threadIdx.x;
    extern __shared__ float sm[];
    float* buf = sm;
    float* qs  = sm + SEQ * HD;
    float* ap  = qs + 4 * HD;
    float* sc  = ap + TT * SEQ;
    __shared__ __align__(16) float vsh[HD];
    __shared__ float ew[SEQ];

    {
        const float4* src = (const float4*)(encproj + (size_t)b * SEQ * HD);
        float4* dst = (float4*)buf;
        for (int i = tid; i < SEQ * HD / 4; i += 256) dst[i] = src[i];
    }
    for (int d = tid; d < HD; d += 256) vsh[d] = v_attn[d];
    if (tid < SEQ) ew[tid] = encw[(size_t)b * SEQ + tid];
    __syncthreads();

    int w = tid >> 5, lane = tid & 31;
    for (int tc = 0; tc < TT; tc += 4) {
        for (int i = tid; i < 4 * HD / 4; i += 256) {
            int t = i / (HD / 4), dd = i % (HD / 4);
            ((float4*)qs)[i] =
                ((const float4*)(qa + ((size_t)(tc + t) * BATCH + b) * 1024))[dd];
        }
        __syncthreads();

        for (int task = w; task < 4 * SEQ; task += 8) {
            int t = task / SEQ, s = task % SEQ;
            const float4* row4 = (const float4*)(buf + s * HD);
            const float4* q4p = (const float4*)(qs + t * HD);
            float acc = 0.f;
#pragma unroll
            for (int j = 0; j < 4; j++) {
                int d4 = lane + j * 32;
                float4 e4 = row4[d4];
                float4 q4 = q4p[d4];
                float4 v4 = *(const float4*)&vsh[d4 * 4];
                acc += tanh_fast(e4.x + q4.x) * v4.x;
                acc += tanh_fast(e4.y + q4.y) * v4.y;
                acc += tanh_fast(e4.z + q4.z) * v4.z;
                acc += tanh_fast(e4.w + q4.w) * v4.w;
            }
#pragma unroll
            for (int o = 16; o; o >>= 1) acc += __shfl_xor_sync(0xffffffffu, acc, o);
            if (lane == 0) sc[t * SEQ + s] = acc;
        }
        __syncthreads();

        if (w < 4) {
            float e = (lane < SEQ) ? __expf(sc[w * SEQ + lane]) : 0.f;
            float sum = e;
#pragma unroll
            for (int o = 16; o; o >>= 1) sum += __shfl_xor_sync(0xffffffffu, sum, o);
            if (lane < SEQ) {
                float a = __fdividef(e, sum);
                ap[(tc + w) * SEQ + lane] = a;
                attn_out[(size_t)b * TT * SEQ + (size_t)(tc + w) * SEQ + lane] = a;
            }
        }
        __syncthreads();
    }

    if (tid < TT) {
        float cd = 0.f;
#pragma unroll
        for (int s = 0; s < SEQ; s++) cd += ap[tid * SEQ + s] * ew[s];
        ctxdot[(size_t)tid * BATCH + b] = cd;
    }
    {
        const float4* src = (const float4*)(ctxw + (size_t)b * SEQ * HD);
        float4* dst = (float4*)buf;
        for (int i = tid; i < SEQ * HD / 4; i += 256) dst[i] = src[i];
    }
    __syncthreads();

    float bap0 = b_ap[tid], bap1 = b_ap[tid + 256];
    for (int t = 0; t < TT; t++) {
        float a0 = 0.f, a1 = 0.f;
        const float* apt = ap + t * SEQ;
#pragma unroll
        for (int s = 0; s < SEQ; s++) {
            float a = apt[s];
            a0 += a * buf[s * HD + tid];
            a1 += a * buf[s * HD + tid + 256];
        }
        const float* qrow = qa + ((size_t)t * BATCH + b) * 1024 + 512;
        size_t base = (size_t)t * BATCH * HD + (size_t)b * HD;
        ah[base + tid]       = __float2half(tanh_fast(qrow[tid] + a0 + bap0));
        ah[base + tid + 256] = __float2half(tanh_fast(qrow[tid + 256] + a1 + bap1));
    }
}

// ---------------- output mix: warp per (t,b) row ----------------
__global__ void out2_k(const float* __restrict__ logits_all,
                       const float* __restrict__ ctxdot,
                       const int* __restrict__ input_char_ids,
                       const float* __restrict__ attn_base,
                       float* __restrict__ outputs)
{
    int warp = threadIdx.x >> 5, lane = threadIdx.x & 31;
    int row = blockIdx.x * 4 + warp;
    int t = row >> 12;
    int b = row & 4095;
    __shared__ float cbuf[4][VOC];

    for (int k = lane; k < VOC; k += 32) cbuf[warp][k] = 0.f;
    __syncwarp();
    if (lane < SEQ) {
        int id = input_char_ids[(size_t)b * SEQ + lane];
        float a = attn_base[(size_t)b * TT * SEQ + (size_t)t * SEQ + lane];
        atomicAdd(&cbuf[warp][id], a);
    }
    __syncwarp();

    const float* lrow = logits_all + (size_t)row * 121;
    float p = sigmoid_fast(lrow[120] + ctxdot[row]);

    float e[4];
    float sum = 0.f;
#pragma unroll
    for (int j = 0; j < 4; j++) {
        int idx = lane + j * 32;
        e[j] = (idx < VOC) ? __expf(lrow[idx]) : 0.f;
        sum += e[j];
    }
#pragma unroll
    for (int o = 16; o; o >>= 1) sum += __shfl_xor_sync(0xffffffffu, sum, o);
    float inv = __fdividef(1.0f - p, sum);
#pragma unroll
    for (int j = 0; j < 4; j++) {
        int idx = lane + j * 32;
        if (idx < VOC)
            outputs[(size_t)b * TT * VOC + (size_t)t * VOC + idx] =
                inv * e[j] + p * cbuf[warp][idx];
    }
}

// ---------------- host ----------------
#define SYM(p, s) cudaGetSymbolAddress((void**)&(p), s)
#define SM128 40960
#define SM64  30720

extern "C" void kernel_launch(void* const* d_in, const int* in_sizes, int n_in,
                              void* d_out, int out_size)
{
    (void)in_sizes; (void)n_in; (void)out_size;
    const float* enc        = (const float*)d_in[0];
    const float* enc_final  = (const float*)d_in[1];
    const int*   tgt        = (const int*)d_in[2];
    const int*   input_ids  = (const int*)d_in[3];
    const float* embed      = (const float*)d_in[4];
    const float* W_init     = (const float*)d_in[5];
    const float* b_init     = (const float*)d_in[6];
    const float* W_ih       = (const float*)d_in[7];
    const float* W_hh       = (const float*)d_in[8];
    const float* b_ih       = (const float*)d_in[9];
    const float* b_hh       = (const float*)d_in[10];
    const float* W_enc_attn = (const float*)d_in[11];
    const float* W_dec_attn = (const float*)d_in[12];
    const float* b_attn     = (const float*)d_in[13];
    const float* v_attn     = (const float*)d_in[14];
    const float* W_ap       = (const float*)d_in[15];
    const float* b_ap       = (const float*)d_in[16];
    const float* W_out      = (const float*)d_in[17];
    const float* b_out      = (const float*)d_in[18];
    const float* w_copy     = (const float*)d_in[19];
    const float* b_copy     = (const float*)d_in[20];

    float* out = (float*)d_out;
    float* outputs   = out;
    float* attn_base = out + (size_t)BATCH * TT * VOC;

    fp16 *ench, *ef, *wg, *wqa, *we, *wapc, *woc, *wi, *h_all, *ah_all;
    float *encproj, *ctxwp, *encw, *embproj, *bqa, *boc, *cst;
    float *qa, *logits_all, *ctxdot;
    SYM(ench, g_ench); SYM(ef, g_ef);
    SYM(encproj, g_encproj); SYM(ctxwp, g_ctxw); SYM(encw, g_encw);
    SYM(embproj, g_embproj);
    SYM(wg, g_wg);     SYM(wqa, g_wqa); SYM(bqa, g_bqa);
    SYM(we, g_we);     SYM(wapc, g_wapc);
    SYM(woc, g_woc);   SYM(boc, g_boc);
    SYM(wi, g_wi);
    SYM(h_all, g_h_all);
    SYM(cst, g_c);     SYM(qa, g_qa);
    SYM(ah_all, g_ah_all);
    SYM(logits_all, g_logits_all); SYM(ctxdot, g_ctxdot);

    // one-time stream/event setup (no device memory allocation)
    static cudaStream_t s2 = nullptr;
    static cudaEvent_t evFork = nullptr, evJoin = nullptr;
    static bool inited = false;
    if (!inited) {
        cudaStreamCreateWithFlags(&s2, cudaStreamNonBlocking);
        cudaEventCreateWithFlags(&evFork, cudaEventDisableTiming);
        cudaEventCreateWithFlags(&evJoin, cudaEventDisableTiming);
        cudaFuncSetAttribute(mma_gemm_k<128, false>,
                             cudaFuncAttributeMaxDynamicSharedMemorySize, SM128);
        cudaFuncSetAttribute(mma_gemm_k<64, true>,
                             cudaFuncAttributeMaxDynamicSharedMemorySize, SM64);
        cudaFuncSetAttribute(comb_cell_k,
                             cudaFuncAttributeMaxDynamicSharedMemorySize, SM64);
        cudaFuncSetAttribute(attnctx_k,
                             cudaFuncAttributeMaxDynamicSharedMemorySize, AC_SMEM);
        inited = true;
    }

    // ---- prep on main (legacy) stream ----
    conv_h_k<<<2048, 256>>>(enc_final, ef, (size_t)BATCH * HE);
    embproj_k<<<dim3(16, VOC), 128>>>(embed, W_ih, b_ih, b_hh, embproj);
    prep_all_k<<<1024, 256>>>(W_hh, W_dec_attn, W_ap, b_attn, W_enc_attn,
                              W_out, b_out, w_copy, b_copy, W_init,
                              wg, wqa, bqa, we, wapc, woc, boc, wi, cst);

    // ---- fork encoder-side chain onto s2 (independent of the recurrence) ----
    cudaEventRecord(evFork, 0);
    cudaStreamWaitEvent(s2, evFork, 0);
    conv_h_k<<<2048, 256, 0, s2>>>(enc, ench, (size_t)BATCH * SEQ * HE);
    encw_k<<<296, 256, 0, s2>>>(enc, w_copy, encw);
    mma_gemm_k<128, false><<<dim3(4, 768), 256, SM128, s2>>>(
        ench, HE, we, HE, nullptr,
        encproj, nullptr, HE, HD);
    mma_gemm_k<128, false><<<dim3(4, 768), 256, SM128, s2>>>(
        ench, HE, wapc, HE, nullptr,
        ctxwp, nullptr, HE, HD);
    cudaEventRecord(evJoin, s2);

    // ---- main stream: h0 then the serial recurrence ----
    mma_gemm_k<64, true><<<dim3(8, 32), 256, SM64>>>(
        ef, HE, wi, HE, b_init,
        nullptr, h_all, HE, HD);
    for (int t = 0; t < TT; t++) {
        size_t off = (size_t)t * BATCH * HD;
        comb_cell_k<<<dim3(32, 32), 256, SM64>>>(
            h_all + off, wg, embproj, tgt,
            cst, h_all + off + (size_t)BATCH * HD, t);
    }

    // deferred: [q | ahp2] for ALL steps: M = T*B, N = 1024, K = 512
    mma_gemm_k<128, false><<<dim3(8, (TT * BATCH) / 128), 256, SM128>>>(
        h_all + (size_t)BATCH * HD, HD, wqa, HD, bqa,
        qa, nullptr, HD, 1024);

    // join encoder chain before attention consumes it
    cudaStreamWaitEvent(0, evJoin, 0);

    // merged attention + ctx + ah finalize + ctxdot
    attnctx_k<<<BATCH, 256, AC_SMEM>>>(
        encproj, ctxwp, encw, qa, v_attn, b_ap, attn_base, ah_all, ctxdot);

    // deferred logits+copy GEMM: M = T*B, N = 121, K = 512
    mma_gemm_k<128, false><<<dim3(1, (TT * BATCH) / 128), 256, SM128>>>(
        ah_all, HD, woc, HD, boc,
        logits_all, nullptr, HD, 121);
    out2_k<<<TT * BATCH / 4, 128>>>(logits_all, ctxdot, input_ids, attn_base, outputs);
}

// round 16
// speedup vs baseline: 1.0686x; 1.0142x over previous
#include <cuda_runtime.h>
#include <cuda_fp16.h>
#include <cstdint>

#define BATCH 4096
#define SEQ   24
#define TT    32
#define VOC   120
#define EMB   128
#define HE    512
#define HD    512
#define START_TOKEN 2
#define NG    2048   // interleaved gates

typedef __half fp16;
typedef unsigned int u32;

// ---------------- device scratch ----------------
__device__ __align__(256) fp16 g_ench[(size_t)BATCH * SEQ * HE];
__device__ __align__(256) fp16 g_ef[(size_t)BATCH * HE];
__device__ __align__(256) fp16 g_encctx[(size_t)BATCH * SEQ * 1024]; // [encproj|ctxw]
__device__ __align__(256) float g_encw[(size_t)BATCH * SEQ];
__device__ __align__(256) float g_embproj[(size_t)VOC * 4 * HD];   // [tok][4d+g]
// weights (single fp16)
__device__ __align__(256) fp16 g_wg[(size_t)NG * HD];              // W_hh interleaved
__device__ __align__(256) fp16 g_wqa[(size_t)1024 * HD];           // [W_dec^T ; W_ap1]
__device__ __align__(256) float g_bqa[1024];
__device__ __align__(256) fp16 g_wec[(size_t)1024 * HD];           // [W_enc^T ; W_ap2]
__device__ __align__(256) fp16 g_woc[(size_t)121 * HD];
__device__ __align__(256) float g_boc[121];
__device__ __align__(256) fp16 g_wi[(size_t)HD * HE];
// activations (single fp16)
__device__ __align__(256) fp16 g_h_all[(size_t)(TT + 1) * BATCH * HD];
__device__ __align__(256) float g_c[(size_t)BATCH * HD];
__device__ __align__(256) float g_qa[(size_t)TT * BATCH * 1024];   // [q | ahp2]
__device__ __align__(256) fp16 g_ah_all[(size_t)TT * BATCH * HD];
__device__ __align__(256) float g_logits_all[(size_t)TT * BATCH * 121];
__device__ __align__(256) float g_ctxdot[(size_t)TT * BATCH];

// ---------------- math helpers ----------------
__device__ __forceinline__ float tanh_fast(float x) {
    float e = __expf(2.0f * x);
    return 1.0f - __fdividef(2.0f, e + 1.0f);
}
__device__ __forceinline__ float sigmoid_fast(float x) {
    return __fdividef(1.0f, 1.0f + __expf(-x));
}

// ---------------- PTX helpers ----------------
__device__ __forceinline__ u32 smem_u32(const void* p) {
    u32 a;
    asm("{ .reg .u64 t; cvta.to.shared.u64 t, %1; cvt.u32.u64 %0, t; }"
        : "=r"(a) : "l"(p));
    return a;
}
__device__ __forceinline__ void cp16(u32 d, const void* s, u32 sz) {
    asm volatile("cp.async.cg.shared.global [%0], [%1], 16, %2;"
                 :: "r"(d), "l"(s), "r"(sz) : "memory");
}
__device__ __forceinline__ void cp_commit() {
    asm volatile("cp.async.commit_group;" ::: "memory");
}
template<int N>
__device__ __forceinline__ void cp_wait() {
    asm volatile("cp.async.wait_group %0;" :: "n"(N) : "memory");
}
__device__ __forceinline__ void ldsm_x4(u32* r, u32 a) {
    asm volatile("ldmatrix.sync.aligned.m8n8.x4.shared.b16 {%0,%1,%2,%3}, [%4];"
                 : "=r"(r[0]), "=r"(r[1]), "=r"(r[2]), "=r"(r[3]) : "r"(a));
}
__device__ __forceinline__ void mma_f16(float* c, const u32* a, const u32* b) {
    asm volatile(
        "mma.sync.aligned.m16n8k16.row.col.f32.f16.f16.f32 "
        "{%0,%1,%2,%3}, {%4,%5,%6,%7}, {%8,%9}, {%0,%1,%2,%3};"
        : "+f"(c[0]), "+f"(c[1]), "+f"(c[2]), "+f"(c[3])
        : "r"(a[0]), "r"(a[1]), "r"(a[2]), "r"(a[3]), "r"(b[0]), "r"(b[1]));
}

// ======== GEMM mainloop: A single fp16, B single fp16 ========
#define GEMM_MAINLOOP(BN, NTN, LDA, LDB, NREAL)                                 \
    constexpr int BUFB = 10240 + (BN) * 80;                                     \
    extern __shared__ char smem[];                                              \
    const u32 sb = smem_u32(smem);                                              \
    const int tid = threadIdx.x, lane = tid & 31, wid = tid >> 5;               \
    const int bm = blockIdx.y * 128, bn = blockIdx.x * (BN);                    \
    const int wm = (wid >> 1) * 32, wn = (wid & 1) * ((BN) / 2);                \
    float acc[2][NTN][4];                                                       \
    _Pragma("unroll") for (int m = 0; m < 2; m++)                               \
    _Pragma("unroll") for (int n = 0; n < NTN; n++)                             \
    _Pragma("unroll") for (int j = 0; j < 4; j++) acc[m][n][j] = 0.0f;          \
    const int nch = K / 32;                                                     \
    auto stage = [&](int c) {                                                   \
        const int kt = c * 32;                                                  \
        const u32 bufb = sb + (u32)(c & 1) * BUFB;                              \
        _Pragma("unroll") for (int p = 0; p < 2; p++) {                         \
            int v = tid + p * 256, row = v >> 2, g = v & 3;                     \
            size_t go = (size_t)(bm + row) * (LDA) + kt + g * 8;                \
            cp16(bufb + row * 80 + g * 16, Aw + go, 16);                        \
        }                                                                       \
        _Pragma("unroll") for (int p = 0; p < (BN) / 64; p++) {                 \
            int v = tid + p * 256, row = v >> 2, g = v & 3;                     \
            int n = bn + row;                                                   \
            int na = (n < (NREAL)) ? n : ((NREAL) - 1);                         \
            u32 sz = (n < (NREAL)) ? 16u : 0u;                                  \
            size_t go = (size_t)na * (LDB) + kt + g * 8;                        \
            cp16(bufb + 10240 + row * 80 + g * 16, Bw + go, sz);                \
        }                                                                       \
    };                                                                          \
    stage(0);                                                                   \
    cp_commit();                                                                \
    for (int c = 0; c < nch; c++) {                                             \
        if (c + 1 < nch) { stage(c + 1); cp_commit(); cp_wait<1>(); }           \
        else             { cp_wait<0>(); }                                      \
        __syncthreads();                                                        \
        const u32 bufb = sb + (u32)(c & 1) * BUFB;                              \
        _Pragma("unroll") for (int k2 = 0; k2 < 2; k2++) {                      \
            const u32 kb = k2 * 32;                                             \
            const u32 a0 = bufb + (wm + (lane & 15)) * 80 + kb + (lane >> 4) * 16; \
            u32 ahf[2][4];                                                      \
            ldsm_x4(ahf[0], a0); ldsm_x4(ahf[1], a0 + 16 * 80);                 \
            const u32 bb0 = bufb + 10240 +                                      \
                (wn + (lane & 7) + ((lane >> 4) & 1) * 8) * 80 +                \
                kb + ((lane >> 3) & 1) * 16;                                    \
            _Pragma("unroll") for (int nt2 = 0; nt2 < (NTN) / 2; nt2++) {       \
                u32 bh4[4];                                                     \
                ldsm_x4(bh4, bb0 + nt2 * 16 * 80);                              \
                _Pragma("unroll") for (int half = 0; half < 2; half++) {        \
                    int nt = nt2 * 2 + half;                                    \
                    const u32* bhf = bh4 + half * 2;                            \
                    _Pragma("unroll") for (int m = 0; m < 2; m++)               \
                        mma_f16(acc[m][nt], ahf[m], bhf);                       \
                }                                                               \
            }                                                                   \
        }                                                                       \
        __syncthreads();                                                        \
    }

// ---------------- generic GEMM ----------------
template<int BN, bool HALFOUT>
__global__ __launch_bounds__(256, 2)
void mma_gemm_k(const fp16* __restrict__ Aw, int lda,
                const fp16* __restrict__ Bw, int ldb,
                const float* __restrict__ bias,
                float* __restrict__ C, fp16* __restrict__ Ch,
                int K, int Nreal)
{
    GEMM_MAINLOOP(BN, BN / 16, lda, ldb, Nreal)

    auto emit = [&](int r, int n, float v) {
        if (n >= Nreal) return;
        size_t o = (size_t)r * Nreal + n;
        if (bias) v += bias[n];
        if (C) C[o] = v;
        if (HALFOUT) Ch[o] = __float2half(v);
    };
#pragma unroll
    for (int m = 0; m < 2; m++) {
        int r0 = bm + wm + m * 16 + (lane >> 2);
#pragma unroll
        for (int nt = 0; nt < BN / 16; nt++) {
            int gn = bn + wn + nt * 8 + (lane & 3) * 2;
            emit(r0,     gn,     acc[m][nt][0]);
            emit(r0,     gn + 1, acc[m][nt][1]);
            emit(r0 + 8, gn,     acc[m][nt][2]);
            emit(r0 + 8, gn + 1, acc[m][nt][3]);
        }
    }
}

// ---------------- fused recurrent gates GEMM + LSTM cell (BN=64) ----------------
__global__ __launch_bounds__(256, 3)
void comb_cell_k(const fp16* __restrict__ Aw,
                 const fp16* __restrict__ Bw,
                 const float* __restrict__ ep,     // [VOC][2048]
                 const int* __restrict__ tgt,
                 float* __restrict__ cst,
                 fp16* __restrict__ hout,
                 int tok_step)
{
    const int K = HD;
    GEMM_MAINLOOP(64, 4, HD, HD, NG)

#pragma unroll
    for (int m = 0; m < 2; m++) {
        int r0 = bm + wm + m * 16 + (lane >> 2);
        int r1 = r0 + 8;
        int tok0 = (tok_step == 0) ? START_TOKEN : tgt[(size_t)r0 * TT + tok_step - 1];
        int tok1 = (tok_step == 0) ? START_TOKEN : tgt[(size_t)r1 * TT + tok_step - 1];
        const float* e0 = ep + (size_t)tok0 * 4 * HD;
        const float* e1 = ep + (size_t)tok1 * 4 * HD;
#pragma unroll
        for (int nt = 0; nt < 4; nt++) {
            int gn = bn + wn + nt * 8 + (lane & 3) * 2;
            float v0 = acc[m][nt][0] + e0[gn];
            float v1 = acc[m][nt][1] + e0[gn + 1];
            float v2 = acc[m][nt][2] + e1[gn];
            float v3 = acc[m][nt][3] + e1[gn + 1];
            float p0 = __shfl_xor_sync(0xffffffffu, v0, 1);
            float p1 = __shfl_xor_sync(0xffffffffu, v1, 1);
            float p2 = __shfl_xor_sync(0xffffffffu, v2, 1);
            float p3 = __shfl_xor_sync(0xffffffffu, v3, 1);
            if (!(lane & 1)) {
                int d = gn >> 2;
                {
                    size_t ci = (size_t)r0 * HD + d;
                    float cn = sigmoid_fast(v1) * cst[ci]
                             + sigmoid_fast(v0) * tanh_fast(p0);
                    cst[ci] = cn;
                    hout[ci] = __float2half(sigmoid_fast(p1) * tanh_fast(cn));
                }
                {
                    size_t ci = (size_t)r1 * HD + d;
                    float cn = sigmoid_fast(v3) * cst[ci]
                             + sigmoid_fast(v2) * tanh_fast(p2);
                    cst[ci] = cn;
                    hout[ci] = __float2half(sigmoid_fast(p3) * tanh_fast(cn));
                }
            }
        }
    }
}

// ---------------- merged weight prep (one launch) ----------------
#define R0 ((size_t)NG * HD)
#define R1 (R0 + (size_t)1024 * HD)
#define R2 (R1 + (size_t)1024 * HD)
#define R3 (R2 + (size_t)121 * HD)
#define R4 (R3 + (size_t)HD * HE)
#define R5 (R4 + (size_t)BATCH * HD)
__global__ void prep_all_k(const float* __restrict__ W_hh,
                           const float* __restrict__ W_dec,
                           const float* __restrict__ W_ap,
                           const float* __restrict__ b_attn,
                           const float* __restrict__ W_enc_attn,
                           const float* __restrict__ W_out,
                           const float* __restrict__ b_out,
                           const float* __restrict__ w_copy,
                           const float* __restrict__ b_copy,
                           const float* __restrict__ W_init,
                           fp16* __restrict__ wg, fp16* __restrict__ wqa,
                           float* __restrict__ bqa,
                           fp16* __restrict__ wec,
                           fp16* __restrict__ woc, float* __restrict__ boc,
                           fp16* __restrict__ wi, float* __restrict__ cst)
{
    for (size_t i = (size_t)blockIdx.x * blockDim.x + threadIdx.x; i < R5;
         i += (size_t)gridDim.x * blockDim.x) {
        if (i < R0) {
            int row = (int)(i / HD), k = (int)(i % HD);
            int src = (row & 3) * HD + (row >> 2);
            wg[i] = __float2half(W_hh[(size_t)src * HD + k]);
        } else if (i < R1) {
            size_t j = i - R0;
            int row = (int)(j / HD), k = (int)(j % HD);
            float v = (row < 512) ? W_dec[(size_t)k * HD + row]
                                  : W_ap[(size_t)(row - 512) * (HD + HE) + k];
            wqa[j] = __float2half(v);
            if (j < 1024) bqa[j] = (j < 512) ? b_attn[j] : 0.0f;
        } else if (i < R2) {
            size_t j = i - R1;
            int row = (int)(j / HD), k = (int)(j % HD);
            // rows 0..511: W_enc_attn^T (encproj); rows 512..1023: W_ap[:,512:] (ctxw)
            float v = (row < 512) ? W_enc_attn[(size_t)k * HD + row]
                                  : W_ap[(size_t)(row - 512) * (HD + HE) + HD + k];
            wec[j] = __float2half(v);
        } else if (i < R3) {
            size_t j = i - R2;
            int row = (int)(j / HD), k = (int)(j % HD);
            float v = (row < VOC) ? W_out[(size_t)row * HD + k] : w_copy[k];
            woc[j] = __float2half(v);
            if (j < 121) boc[j] = (j < VOC) ? b_out[j] : b_copy[0];
        } else if (i < R4) {
            size_t j = i - R3;
            wi[j] = __float2half(W_init[j]);
        } else {
            cst[i - R4] = 0.0f;
        }
    }
}

// vectorized fp32 -> fp16: 8 elements per thread
__global__ void conv_h8_k(const float* __restrict__ src, fp16* __restrict__ dst,
                          size_t n8)
{
    for (size_t i = (size_t)blockIdx.x * blockDim.x + threadIdx.x; i < n8;
         i += (size_t)gridDim.x * blockDim.x) {
        float4 a = ((const float4*)src)[i * 2];
        float4 b = ((const float4*)src)[i * 2 + 1];
        __half2 h0 = __floats2half2_rn(a.x, a.y);
        __half2 h1 = __floats2half2_rn(a.z, a.w);
        __half2 h2 = __floats2half2_rn(b.x, b.y);
        __half2 h3 = __floats2half2_rn(b.z, b.w);
        uint4 o;
        o.x = *(u32*)&h0; o.y = *(u32*)&h1; o.z = *(u32*)&h2; o.w = *(u32*)&h3;
        ((uint4*)dst)[i] = o;
    }
}

__global__ void embproj_k(const float* __restrict__ embed,
                          const float* __restrict__ W_ih,
                          const float* __restrict__ b_ih,
                          const float* __restrict__ b_hh,
                          float* __restrict__ ep)
{
    int v = blockIdx.y;
    int n = blockIdx.x * 128 + threadIdx.x;
    int j = (n & 3) * HD + (n >> 2);
    __shared__ float em[EMB];
    if (threadIdx.x < EMB) em[threadIdx.x] = embed[(size_t)v * EMB + threadIdx.x];
    __syncthreads();
    float acc = b_ih[j] + b_hh[j];
    const float* w = W_ih + (size_t)j * EMB;
#pragma unroll 8
    for (int k = 0; k < EMB; k++) acc += em[k] * w[k];
    ep[(size_t)v * 4 * HD + n] = acc;
}

// warp per row, grid-stride
__global__ void encw_k(const float* __restrict__ enc,
                       const float* __restrict__ w_copy,
                       float* __restrict__ encw)
{
    __shared__ __align__(16) float wsh[HE];
    for (int k = threadIdx.x; k < HE; k += blockDim.x) wsh[k] = w_copy[HD + k];
    __syncthreads();
    int lane = threadIdx.x & 31;
    int gw = (blockIdx.x * blockDim.x + threadIdx.x) >> 5;
    int nw = (gridDim.x * blockDim.x) >> 5;
    for (int r = gw; r < BATCH * SEQ; r += nw) {
        const float4* row = (const float4*)(enc + (size_t)r * HE);
        float acc = 0.f;
#pragma unroll
        for (int j = 0; j < 4; j++) {
            int d4 = lane + j * 32;
            float4 v = row[d4];
            float4 w = *(const float4*)&wsh[d4 * 4];
            acc += v.x * w.x + v.y * w.y + v.z * w.z + v.w * w.w;
        }
#pragma unroll
        for (int o = 16; o; o >>= 1) acc += __shfl_xor_sync(0xffffffffu, acc, o);
        if (lane == 0) encw[r] = acc;
    }
}

// ---------------- merged attention + ctx pass: block per b ----------------
// encctx: [b*SEQ+s][1024] fp16; cols 0..511 encproj, 512..1023 ctxw
#define AC_SMEM ((SEQ * HD + 4 * HD + TT * SEQ + 4 * SEQ) * 4)
__global__ __launch_bounds__(256)
void attnctx_k(const fp16* __restrict__ encctx,
               const float* __restrict__ encw,
               const float* __restrict__ qa,
               const float* __restrict__ v_attn,
               const float* __restrict__ b_ap,
               float* __restrict__ attn_out,
               fp16* __restrict__ ah,
               float* __restrict__ ctxdot)
{
    int b = blockIdx.x;
    int tid = threadIdx.x;
    extern __shared__ float sm[];
    float* buf = sm;
    float* qs  = sm + SEQ * HD;
    float* ap  = qs + 4 * HD;
    float* sc  = ap + TT * SEQ;
    __shared__ __align__(16) float vsh[HD];
    __shared__ float ew[SEQ];

    // stage encproj half of encctx (fp16 -> fp32 smem)
    for (int i = tid; i < SEQ * HD / 8; i += 256) {
        int idx = i * 8;
        int s = idx >> 9, d = idx & 511;
        uint4 v = *(const uint4*)(encctx + ((size_t)b * SEQ + s) * 1024 + d);
        float2 f0 = __half22float2(*(__half2*)&v.x);
        float2 f1 = __half22float2(*(__half2*)&v.y);
        float2 f2 = __half22float2(*(__half2*)&v.z);
        float2 f3 = __half22float2(*(__half2*)&v.w);
        float* o = buf + s * HD + d;
        o[0] = f0.x; o[1] = f0.y; o[2] = f1.x; o[3] = f1.y;
        o[4] = f2.x; o[5] = f2.y; o[6] = f3.x; o[7] = f3.y;
    }
    for (int d = tid; d < HD; d += 256) vsh[d] = v_attn[d];
    if (tid < SEQ) ew[tid] = encw[(size_t)b * SEQ + tid];
    __syncthreads();

    int w = tid >> 5, lane = tid & 31;
    for (int tc = 0; tc < TT; tc += 4) {
        for (int i = tid; i < 4 * HD / 4; i += 256) {
            int t = i / (HD / 4), dd = i % (HD / 4);
            ((float4*)qs)[i] =
                ((const float4*)(qa + ((size_t)(tc + t) * BATCH + b) * 1024))[dd];
        }
        __syncthreads();

        for (int task = w; task < 4 * SEQ; task += 8) {
            int t = task / SEQ, s = task % SEQ;
            const float4* row4 = (const float4*)(buf + s * HD);
            const float4* q4p = (const float4*)(qs + t * HD);
            float acc = 0.f;
#pragma unroll
            for (int j = 0; j < 4; j++) {
                int d4 = lane + j * 32;
                float4 e4 = row4[d4];
                float4 q4 = q4p[d4];
                float4 v4 = *(const float4*)&vsh[d4 * 4];
                acc += tanh_fast(e4.x + q4.x) * v4.x;
                acc += tanh_fast(e4.y + q4.y) * v4.y;
                acc += tanh_fast(e4.z + q4.z) * v4.z;
                acc += tanh_fast(e4.w + q4.w) * v4.w;
            }
#pragma unroll
            for (int o = 16; o; o >>= 1) acc += __shfl_xor_sync(0xffffffffu, acc, o);
            if (lane == 0) sc[t * SEQ + s] = acc;
        }
        __syncthreads();

        if (w < 4) {
            float e = (lane < SEQ) ? __expf(sc[w * SEQ + lane]) : 0.f;
            float sum = e;
#pragma unroll
            for (int o = 16; o; o >>= 1) sum += __shfl_xor_sync(0xffffffffu, sum, o);
            if (lane < SEQ) {
                float a = __fdividef(e, sum);
                ap[(tc + w) * SEQ + lane] = a;
                attn_out[(size_t)b * TT * SEQ + (size_t)(tc + w) * SEQ + lane] = a;
            }
        }
        __syncthreads();
    }

    if (tid < TT) {
        float cd = 0.f;
#pragma unroll
        for (int s = 0; s < SEQ; s++) cd += ap[tid * SEQ + s] * ew[s];
        ctxdot[(size_t)tid * BATCH + b] = cd;
    }
    // restage ctxw half of encctx
    for (int i = tid; i < SEQ * HD / 8; i += 256) {
        int idx = i * 8;
        int s = idx >> 9, d = idx & 511;
        uint4 v = *(const uint4*)(encctx + ((size_t)b * SEQ + s) * 1024 + 512 + d);
        float2 f0 = __half22float2(*(__half2*)&v.x);
        float2 f1 = __half22float2(*(__half2*)&v.y);
        float2 f2 = __half22float2(*(__half2*)&v.z);
        float2 f3 = __half22float2(*(__half2*)&v.w);
        float* o = buf + s * HD + d;
        o[0] = f0.x; o[1] = f0.y; o[2] = f1.x; o[3] = f1.y;
        o[4] = f2.x; o[5] = f2.y; o[6] = f3.x; o[7] = f3.y;
    }
    __syncthreads();

    float bap0 = b_ap[tid], bap1 = b_ap[tid + 256];
    for (int t = 0; t < TT; t++) {
        float a0 = 0.f, a1 = 0.f;
        const float* apt = ap + t * SEQ;
#pragma unroll
        for (int s = 0; s < SEQ; s++) {
            float a = apt[s];
            a0 += a * buf[s * HD + tid];
            a1 += a * buf[s * HD + tid + 256];
        }
        const float* qrow = qa + ((size_t)t * BATCH + b) * 1024 + 512;
        size_t base = (size_t)t * BATCH * HD + (size_t)b * HD;
        ah[base + tid]       = __float2half(tanh_fast(qrow[tid] + a0 + bap0));
        ah[base + tid + 256] = __float2half(tanh_fast(qrow[tid + 256] + a1 + bap1));
    }
}

// ---------------- output mix: warp per (t,b) row ----------------
__global__ void out2_k(const float* __restrict__ logits_all,
                       const float* __restrict__ ctxdot,
                       const int* __restrict__ input_char_ids,
                       const float* __restrict__ attn_base,
                       float* __restrict__ outputs)
{
    int warp = threadIdx.x >> 5, lane = threadIdx.x & 31;
    int row = blockIdx.x * 4 + warp;
    int t = row >> 12;
    int b = row & 4095;
    __shared__ float cbuf[4][VOC];

    for (int k = lane; k < VOC; k += 32) cbuf[warp][k] = 0.f;
    __syncwarp();
    if (lane < SEQ) {
        int id = input_char_ids[(size_t)b * SEQ + lane];
        float a = attn_base[(size_t)b * TT * SEQ + (size_t)t * SEQ + lane];
        atomicAdd(&cbuf[warp][id], a);
    }
    __syncwarp();

    const float* lrow = logits_all + (size_t)row * 121;
    float p = sigmoid_fast(lrow[120] + ctxdot[row]);

    float e[4];
    float sum = 0.f;
#pragma unroll
    for (int j = 0; j < 4; j++) {
        int idx = lane + j * 32;
        e[j] = (idx < VOC) ? __expf(lrow[idx]) : 0.f;
        sum += e[j];
    }
#pragma unroll
    for (int o = 16; o; o >>= 1) sum += __shfl_xor_sync(0xffffffffu, sum, o);
    float inv = __fdividef(1.0f - p, sum);
#pragma unroll
    for (int j = 0; j < 4; j++) {
        int idx = lane + j * 32;
        if (idx < VOC)
            outputs[(size_t)b * TT * VOC + (size_t)t * VOC + idx] =
                inv * e[j] + p * cbuf[warp][idx];
    }
}

// ---------------- host ----------------
#define SYM(p, s) cudaGetSymbolAddress((void**)&(p), s)
#define SM128 40960
#define SM64  30720

extern "C" void kernel_launch(void* const* d_in, const int* in_sizes, int n_in,
                              void* d_out, int out_size)
{
    (void)in_sizes; (void)n_in; (void)out_size;
    const float* enc        = (const float*)d_in[0];
    const float* enc_final  = (const float*)d_in[1];
    const int*   tgt        = (const int*)d_in[2];
    const int*   input_ids  = (const int*)d_in[3];
    const float* embed      = (const float*)d_in[4];
    const float* W_init     = (const float*)d_in[5];
    const float* b_init     = (const float*)d_in[6];
    const float* W_ih       = (const float*)d_in[7];
    const float* W_hh       = (const float*)d_in[8];
    const float* b_ih       = (const float*)d_in[9];
    const float* b_hh       = (const float*)d_in[10];
    const float* W_enc_attn = (const float*)d_in[11];
    const float* W_dec_attn = (const float*)d_in[12];
    const float* b_attn     = (const float*)d_in[13];
    const float* v_attn     = (const float*)d_in[14];
    const float* W_ap       = (const float*)d_in[15];
    const float* b_ap       = (const float*)d_in[16];
    const float* W_out      = (const float*)d_in[17];
    const float* b_out      = (const float*)d_in[18];
    const float* w_copy     = (const float*)d_in[19];
    const float* b_copy     = (const float*)d_in[20];

    float* out = (float*)d_out;
    float* outputs   = out;
    float* attn_base = out + (size_t)BATCH * TT * VOC;

    fp16 *ench, *ef, *encctx, *wg, *wqa, *wec, *woc, *wi, *h_all, *ah_all;
    float *encw, *embproj, *bqa, *boc, *cst;
    float *qa, *logits_all, *ctxdot;
    SYM(ench, g_ench); SYM(ef, g_ef);
    SYM(encctx, g_encctx); SYM(encw, g_encw);
    SYM(embproj, g_embproj);
    SYM(wg, g_wg);     SYM(wqa, g_wqa); SYM(bqa, g_bqa);
    SYM(wec, g_wec);
    SYM(woc, g_woc);   SYM(boc, g_boc);
    SYM(wi, g_wi);
    SYM(h_all, g_h_all);
    SYM(cst, g_c);     SYM(qa, g_qa);
    SYM(ah_all, g_ah_all);
    SYM(logits_all, g_logits_all); SYM(ctxdot, g_ctxdot);

    // one-time stream/event setup (no device memory allocation)
    static cudaStream_t s2 = nullptr;
    static cudaEvent_t evFork = nullptr, evJoin = nullptr;
    static bool inited = false;
    if (!inited) {
        cudaStreamCreateWithFlags(&s2, cudaStreamNonBlocking);
        cudaEventCreateWithFlags(&evFork, cudaEventDisableTiming);
        cudaEventCreateWithFlags(&evJoin, cudaEventDisableTiming);
        cudaFuncSetAttribute(mma_gemm_k<128, false>,
                             cudaFuncAttributeMaxDynamicSharedMemorySize, SM128);
        cudaFuncSetAttribute(mma_gemm_k<128, true>,
                             cudaFuncAttributeMaxDynamicSharedMemorySize, SM128);
        cudaFuncSetAttribute(mma_gemm_k<64, true>,
                             cudaFuncAttributeMaxDynamicSharedMemorySize, SM64);
        cudaFuncSetAttribute(comb_cell_k,
                             cudaFuncAttributeMaxDynamicSharedMemorySize, SM64);
        cudaFuncSetAttribute(attnctx_k,
                             cudaFuncAttributeMaxDynamicSharedMemorySize, AC_SMEM);
        inited = true;
    }

    // ---- prep on main (legacy) stream ----
    conv_h8_k<<<1024, 256>>>(enc_final, ef, (size_t)BATCH * HE / 8);
    embproj_k<<<dim3(16, VOC), 128>>>(embed, W_ih, b_ih, b_hh, embproj);
    prep_all_k<<<1024, 256>>>(W_hh, W_dec_attn, W_ap, b_attn, W_enc_attn,
                              W_out, b_out, w_copy, b_copy, W_init,
                              wg, wqa, bqa, wec, woc, boc, wi, cst);

    // ---- fork encoder-side chain onto s2 ----
    cudaEventRecord(evFork, 0);
    cudaStreamWaitEvent(s2, evFork, 0);
    conv_h8_k<<<2048, 256, 0, s2>>>(enc, ench, (size_t)BATCH * SEQ * HE / 8);
    encw_k<<<296, 256, 0, s2>>>(enc, w_copy, encw);
    // encctx = enc @ [W_enc^T ; W_ap2]^T  (N=1024, fp16 out)
    mma_gemm_k<128, true><<<dim3(8, 768), 256, SM128, s2>>>(
        ench, HE, wec, HE, nullptr,
        nullptr, encctx, HE, 1024);
    cudaEventRecord(evJoin, s2);

    // ---- main stream: h0 then the serial recurrence ----
    mma_gemm_k<64, true><<<dim3(8, 32), 256, SM64>>>(
        ef, HE, wi, HE, b_init,
        nullptr, h_all, HE, HD);
    for (int t = 0; t < TT; t++) {
        size_t off = (size_t)t * BATCH * HD;
        comb_cell_k<<<dim3(32, 32), 256, SM64>>>(
            h_all + off, wg, embproj, tgt,
            cst, h_all + off + (size_t)BATCH * HD, t);
    }

    // deferred: [q | ahp2] for ALL steps: M = T*B, N = 1024, K = 512
    mma_gemm_k<128, false><<<dim3(8, (TT * BATCH) / 128), 256, SM128>>>(
        h_all + (size_t)BATCH * HD, HD, wqa, HD, bqa,
        qa, nullptr, HD, 1024);

    // join encoder chain before attention consumes it
    cudaStreamWaitEvent(0, evJoin, 0);

    // merged attention + ctx + ah finalize + ctxdot
    attnctx_k<<<BATCH, 256, AC_SMEM>>>(
        encctx, encw, qa, v_attn, b_ap, attn_base, ah_all, ctxdot);

    // deferred logits+copy GEMM: M = T*B, N = 121, K = 512
    mma_gemm_k<128, false><<<dim3(1, (TT * BATCH) / 128), 256, SM128>>>(
        ah_all, HD, woc, HD, boc,
        logits_all, nullptr, HD, 121);
    out2_k<<<TT * BATCH / 4, 128>>>(logits_all, ctxdot, input_ids, attn_base, outputs);
}

// round 17
// speedup vs baseline: 1.1329x; 1.0602x over previous
#include <cuda_runtime.h>
#include <cuda_fp16.h>
#include <cstdint>

#define BATCH 4096
#define SEQ   24
#define TT    32
#define VOC   120
#define EMB   128
#define HE    512
#define HD    512
#define START_TOKEN 2
#define NG    2048   // interleaved gates

typedef __half fp16;
typedef unsigned int u32;

// ---------------- device scratch ----------------
__device__ __align__(256) fp16 g_ench[(size_t)BATCH * SEQ * HE];
__device__ __align__(256) fp16 g_ef[(size_t)BATCH * HE];
__device__ __align__(256) fp16 g_encctx[(size_t)BATCH * SEQ * 1024]; // [encproj|ctxw]
__device__ __align__(256) float g_encw[(size_t)BATCH * SEQ];
__device__ __align__(256) float g_embproj[(size_t)VOC * 4 * HD];   // [tok][4d+g]
// weights (single fp16)
__device__ __align__(256) fp16 g_wg[(size_t)NG * HD];              // W_hh interleaved
__device__ __align__(256) fp16 g_wqa[(size_t)1024 * HD];           // [W_dec^T ; W_ap1]
__device__ __align__(256) float g_bqa[1024];
__device__ __align__(256) fp16 g_wec[(size_t)1024 * HD];           // [W_enc^T ; W_ap2]
__device__ __align__(256) fp16 g_woc[(size_t)121 * HD];
__device__ __align__(256) float g_boc[121];
__device__ __align__(256) fp16 g_wi[(size_t)HD * HE];
// activations (single fp16)
__device__ __align__(256) fp16 g_h_all[(size_t)(TT + 1) * BATCH * HD];
__device__ __align__(256) float g_c[(size_t)BATCH * HD];
__device__ __align__(256) float g_qa[(size_t)TT * BATCH * 1024];   // [q | ahp2]
__device__ __align__(256) fp16 g_ah_all[(size_t)TT * BATCH * HD];
__device__ __align__(256) float g_logits_all[(size_t)TT * BATCH * 121];
__device__ __align__(256) float g_ctxdot[(size_t)TT * BATCH];

// ---------------- math helpers ----------------
__device__ __forceinline__ float tanh_fast(float x) {
    float e = __expf(2.0f * x);
    return 1.0f - __fdividef(2.0f, e + 1.0f);
}
__device__ __forceinline__ float sigmoid_fast(float x) {
    return __fdividef(1.0f, 1.0f + __expf(-x));
}

// ---------------- PTX helpers ----------------
__device__ __forceinline__ u32 smem_u32(const void* p) {
    u32 a;
    asm("{ .reg .u64 t; cvta.to.shared.u64 t, %1; cvt.u32.u64 %0, t; }"
        : "=r"(a) : "l"(p));
    return a;
}
__device__ __forceinline__ void cp16(u32 d, const void* s, u32 sz) {
    asm volatile("cp.async.cg.shared.global [%0], [%1], 16, %2;"
                 :: "r"(d), "l"(s), "r"(sz) : "memory");
}
__device__ __forceinline__ void cp_commit() {
    asm volatile("cp.async.commit_group;" ::: "memory");
}
template<int N>
__device__ __forceinline__ void cp_wait() {
    asm volatile("cp.async.wait_group %0;" :: "n"(N) : "memory");
}
__device__ __forceinline__ void ldsm_x4(u32* r, u32 a) {
    asm volatile("ldmatrix.sync.aligned.m8n8.x4.shared.b16 {%0,%1,%2,%3}, [%4];"
                 : "=r"(r[0]), "=r"(r[1]), "=r"(r[2]), "=r"(r[3]) : "r"(a));
}
__device__ __forceinline__ void mma_f16(float* c, const u32* a, const u32* b) {
    asm volatile(
        "mma.sync.aligned.m16n8k16.row.col.f32.f16.f16.f32 "
        "{%0,%1,%2,%3}, {%4,%5,%6,%7}, {%8,%9}, {%0,%1,%2,%3};"
        : "+f"(c[0]), "+f"(c[1]), "+f"(c[2]), "+f"(c[3])
        : "r"(a[0]), "r"(a[1]), "r"(a[2]), "r"(a[3]), "r"(b[0]), "r"(b[1]));
}

// ======== GEMM mainloop: A fp16, B fp16, K-chunk = KC (32 or 64) ========
// per-buffer: A = 128 rows x RS, B = BN rows x RS; RS = 2*KC + 16 bytes.
#define GEMM_MAINLOOP(BN, NTN, KC, LDA, LDB, NREAL)                             \
    constexpr int RS   = 2 * (KC) + 16;                                         \
    constexpr int AOFF = 128 * RS;                                              \
    constexpr int BUFB = (128 + (BN)) * RS;                                     \
    extern __shared__ char smem[];                                              \
    const u32 sb = smem_u32(smem);                                              \
    const int tid = threadIdx.x, lane = tid & 31, wid = tid >> 5;               \
    const int bm = blockIdx.y * 128, bn = blockIdx.x * (BN);                    \
    const int wm = (wid >> 1) * 32, wn = (wid & 1) * ((BN) / 2);                \
    float acc[2][NTN][4];                                                       \
    _Pragma("unroll") for (int m = 0; m < 2; m++)                               \
    _Pragma("unroll") for (int n = 0; n < NTN; n++)                             \
    _Pragma("unroll") for (int j = 0; j < 4; j++) acc[m][n][j] = 0.0f;          \
    const int nch = K / (KC);                                                   \
    auto stage = [&](int c) {                                                   \
        const int kt = c * (KC);                                                \
        const u32 bufb = sb + (u32)(c & 1) * BUFB;                              \
        _Pragma("unroll") for (int p = 0; p < (KC) / 16; p++) {                 \
            int v = tid + p * 256;                                              \
            int row = v / ((KC) / 8), g = v % ((KC) / 8);                       \
            size_t go = (size_t)(bm + row) * (LDA) + kt + g * 8;                \
            cp16(bufb + row * RS + g * 16, Aw + go, 16);                        \
        }                                                                       \
        _Pragma("unroll") for (int p = 0; p < (BN) * (KC) / 2048; p++) {        \
            int v = tid + p * 256;                                              \
            int row = v / ((KC) / 8), g = v % ((KC) / 8);                       \
            int n = bn + row;                                                   \
            int na = (n < (NREAL)) ? n : ((NREAL) - 1);                         \
            u32 sz = (n < (NREAL)) ? 16u : 0u;                                  \
            size_t go = (size_t)na * (LDB) + kt + g * 8;                        \
            cp16(bufb + AOFF + row * RS + g * 16, Bw + go, sz);                 \
        }                                                                       \
    };                                                                          \
    stage(0);                                                                   \
    cp_commit();                                                                \
    for (int c = 0; c < nch; c++) {                                             \
        if (c + 1 < nch) { stage(c + 1); cp_commit(); cp_wait<1>(); }           \
        else             { cp_wait<0>(); }                                      \
        __syncthreads();                                                        \
        const u32 bufb = sb + (u32)(c & 1) * BUFB;                              \
        _Pragma("unroll") for (int k2 = 0; k2 < (KC) / 16; k2++) {              \
            const u32 kb = k2 * 32;                                             \
            const u32 a0 = bufb + (wm + (lane & 15)) * RS + kb + (lane >> 4) * 16; \
            u32 ahf[2][4];                                                      \
            ldsm_x4(ahf[0], a0); ldsm_x4(ahf[1], a0 + 16 * RS);                 \
            const u32 bb0 = bufb + AOFF +                                       \
                (wn + (lane & 7) + ((lane >> 4) & 1) * 8) * RS +                \
                kb + ((lane >> 3) & 1) * 16;                                    \
            _Pragma("unroll") for (int nt2 = 0; nt2 < (NTN) / 2; nt2++) {       \
                u32 bh4[4];                                                     \
                ldsm_x4(bh4, bb0 + nt2 * 16 * RS);                              \
                _Pragma("unroll") for (int half = 0; half < 2; half++) {        \
                    int nt = nt2 * 2 + half;                                    \
                    const u32* bhf = bh4 + half * 2;                            \
                    _Pragma("unroll") for (int m = 0; m < 2; m++)               \
                        mma_f16(acc[m][nt], ahf[m], bhf);                       \
                }                                                               \
            }                                                                   \
        }                                                                       \
        __syncthreads();                                                        \
    }

// ---------------- generic GEMM (KC=64) ----------------
template<int BN, bool HALFOUT>
__global__ __launch_bounds__(256, 2)
void mma_gemm_k(const fp16* __restrict__ Aw, int lda,
                const fp16* __restrict__ Bw, int ldb,
                const float* __restrict__ bias,
                float* __restrict__ C, fp16* __restrict__ Ch,
                int K, int Nreal)
{
    GEMM_MAINLOOP(BN, BN / 16, 64, lda, ldb, Nreal)

    auto emit = [&](int r, int n, float v) {
        if (n >= Nreal) return;
        size_t o = (size_t)r * Nreal + n;
        if (bias) v += bias[n];
        if (C) C[o] = v;
        if (HALFOUT) Ch[o] = __float2half(v);
    };
#pragma unroll
    for (int m = 0; m < 2; m++) {
        int r0 = bm + wm + m * 16 + (lane >> 2);
#pragma unroll
        for (int nt = 0; nt < BN / 16; nt++) {
            int gn = bn + wn + nt * 8 + (lane & 3) * 2;
            emit(r0,     gn,     acc[m][nt][0]);
            emit(r0,     gn + 1, acc[m][nt][1]);
            emit(r0 + 8, gn,     acc[m][nt][2]);
            emit(r0 + 8, gn + 1, acc[m][nt][3]);
        }
    }
}

// ---------------- fused recurrent gates GEMM + LSTM cell (BN=64, KC=64) ----------------
__global__ __launch_bounds__(256, 3)
void comb_cell_k(const fp16* __restrict__ Aw,
                 const fp16* __restrict__ Bw,
                 const float* __restrict__ ep,     // [VOC][2048]
                 const int* __restrict__ tgt,
                 float* __restrict__ cst,
                 fp16* __restrict__ hout,
                 int tok_step)
{
    const int K = HD;
    GEMM_MAINLOOP(64, 4, 64, HD, HD, NG)

#pragma unroll
    for (int m = 0; m < 2; m++) {
        int r0 = bm + wm + m * 16 + (lane >> 2);
        int r1 = r0 + 8;
        int tok0 = (tok_step == 0) ? START_TOKEN : tgt[(size_t)r0 * TT + tok_step - 1];
        int tok1 = (tok_step == 0) ? START_TOKEN : tgt[(size_t)r1 * TT + tok_step - 1];
        const float* e0 = ep + (size_t)tok0 * 4 * HD;
        const float* e1 = ep + (size_t)tok1 * 4 * HD;
#pragma unroll
        for (int nt = 0; nt < 4; nt++) {
            int gn = bn + wn + nt * 8 + (lane & 3) * 2;
            float v0 = acc[m][nt][0] + e0[gn];
            float v1 = acc[m][nt][1] + e0[gn + 1];
            float v2 = acc[m][nt][2] + e1[gn];
            float v3 = acc[m][nt][3] + e1[gn + 1];
            float p0 = __shfl_xor_sync(0xffffffffu, v0, 1);
            float p1 = __shfl_xor_sync(0xffffffffu, v1, 1);
            float p2 = __shfl_xor_sync(0xffffffffu, v2, 1);
            float p3 = __shfl_xor_sync(0xffffffffu, v3, 1);
            if (!(lane & 1)) {
                int d = gn >> 2;
                {
                    size_t ci = (size_t)r0 * HD + d;
                    float cn = sigmoid_fast(v1) * cst[ci]
                             + sigmoid_fast(v0) * tanh_fast(p0);
                    cst[ci] = cn;
                    hout[ci] = __float2half(sigmoid_fast(p1) * tanh_fast(cn));
                }
                {
                    size_t ci = (size_t)r1 * HD + d;
                    float cn = sigmoid_fast(v3) * cst[ci]
                             + sigmoid_fast(v2) * tanh_fast(p2);
                    cst[ci] = cn;
                    hout[ci] = __float2half(sigmoid_fast(p3) * tanh_fast(cn));
                }
            }
        }
    }
}

// ---------------- merged weight prep (one launch) ----------------
#define R0 ((size_t)NG * HD)
#define R1 (R0 + (size_t)1024 * HD)
#define R2 (R1 + (size_t)1024 * HD)
#define R3 (R2 + (size_t)121 * HD)
#define R4 (R3 + (size_t)HD * HE)
#define R5 (R4 + (size_t)BATCH * HD)
__global__ void prep_all_k(const float* __restrict__ W_hh,
                           const float* __restrict__ W_dec,
                           const float* __restrict__ W_ap,
                           const float* __restrict__ b_attn,
                           const float* __restrict__ W_enc_attn,
                           const float* __restrict__ W_out,
                           const float* __restrict__ b_out,
                           const float* __restrict__ w_copy,
                           const float* __restrict__ b_copy,
                           const float* __restrict__ W_init,
                           fp16* __restrict__ wg, fp16* __restrict__ wqa,
                           float* __restrict__ bqa,
                           fp16* __restrict__ wec,
                           fp16* __restrict__ woc, float* __restrict__ boc,
                           fp16* __restrict__ wi, float* __restrict__ cst)
{
    for (size_t i = (size_t)blockIdx.x * blockDim.x + threadIdx.x; i < R5;
         i += (size_t)gridDim.x * blockDim.x) {
        if (i < R0) {
            int row = (int)(i / HD), k = (int)(i % HD);
            int src = (row & 3) * HD + (row >> 2);
            wg[i] = __float2half(W_hh[(size_t)src * HD + k]);
        } else if (i < R1) {
            size_t j = i - R0;
            int row = (int)(j / HD), k = (int)(j % HD);
            float v = (row < 512) ? W_dec[(size_t)k * HD + row]
                                  : W_ap[(size_t)(row - 512) * (HD + HE) + k];
            wqa[j] = __float2half(v);
            if (j < 1024) bqa[j] = (j < 512) ? b_attn[j] : 0.0f;
        } else if (i < R2) {
            size_t j = i - R1;
            int row = (int)(j / HD), k = (int)(j % HD);
            float v = (row < 512) ? W_enc_attn[(size_t)k * HD + row]
                                  : W_ap[(size_t)(row - 512) * (HD + HE) + HD + k];
            wec[j] = __float2half(v);
        } else if (i < R3) {
            size_t j = i - R2;
            int row = (int)(j / HD), k = (int)(j % HD);
            float v = (row < VOC) ? W_out[(size_t)row * HD + k] : w_copy[k];
            woc[j] = __float2half(v);
            if (j < 121) boc[j] = (j < VOC) ? b_out[j] : b_copy[0];
        } else if (i < R4) {
            size_t j = i - R3;
            wi[j] = __float2half(W_init[j]);
        } else {
            cst[i - R4] = 0.0f;
        }
    }
}

// vectorized fp32 -> fp16: 8 elements per thread
__global__ void conv_h8_k(const float* __restrict__ src, fp16* __restrict__ dst,
                          size_t n8)
{
    for (size_t i = (size_t)blockIdx.x * blockDim.x + threadIdx.x; i < n8;
         i += (size_t)gridDim.x * blockDim.x) {
        float4 a = ((const float4*)src)[i * 2];
        float4 b = ((const float4*)src)[i * 2 + 1];
        __half2 h0 = __floats2half2_rn(a.x, a.y);
        __half2 h1 = __floats2half2_rn(a.z, a.w);
        __half2 h2 = __floats2half2_rn(b.x, b.y);
        __half2 h3 = __floats2half2_rn(b.z, b.w);
        uint4 o;
        o.x = *(u32*)&h0; o.y = *(u32*)&h1; o.z = *(u32*)&h2; o.w = *(u32*)&h3;
        ((uint4*)dst)[i] = o;
    }
}

__global__ void embproj_k(const float* __restrict__ embed,
                          const float* __restrict__ W_ih,
                          const float* __restrict__ b_ih,
                          const float* __restrict__ b_hh,
                          float* __restrict__ ep)
{
    int v = blockIdx.y;
    int n = blockIdx.x * 128 + threadIdx.x;
    int j = (n & 3) * HD + (n >> 2);
    __shared__ float em[EMB];
    if (threadIdx.x < EMB) em[threadIdx.x] = embed[(size_t)v * EMB + threadIdx.x];
    __syncthreads();
    float acc = b_ih[j] + b_hh[j];
    const float* w = W_ih + (size_t)j * EMB;
#pragma unroll 8
    for (int k = 0; k < EMB; k++) acc += em[k] * w[k];
    ep[(size_t)v * 4 * HD + n] = acc;
}

// warp per row, grid-stride
__global__ void encw_k(const float* __restrict__ enc,
                       const float* __restrict__ w_copy,
                       float* __restrict__ encw)
{
    __shared__ __align__(16) float wsh[HE];
    for (int k = threadIdx.x; k < HE; k += blockDim.x) wsh[k] = w_copy[HD + k];
    __syncthreads();
    int lane = threadIdx.x & 31;
    int gw = (blockIdx.x * blockDim.x + threadIdx.x) >> 5;
    int nw = (gridDim.x * blockDim.x) >> 5;
    for (int r = gw; r < BATCH * SEQ; r += nw) {
        const float4* row = (const float4*)(enc + (size_t)r * HE);
        float acc = 0.f;
#pragma unroll
        for (int j = 0; j < 4; j++) {
            int d4 = lane + j * 32;
            float4 v = row[d4];
            float4 w = *(const float4*)&wsh[d4 * 4];
            acc += v.x * w.x + v.y * w.y + v.z * w.z + v.w * w.w;
        }
#pragma unroll
        for (int o = 16; o; o >>= 1) acc += __shfl_xor_sync(0xffffffffu, acc, o);
        if (lane == 0) encw[r] = acc;
    }
}

// ---------------- merged attention + ctx pass: block per b ----------------
#define AC_SMEM ((SEQ * HD + 4 * HD + TT * SEQ + 4 * SEQ) * 4)
__global__ __launch_bounds__(256)
void attnctx_k(const fp16* __restrict__ encctx,
               const float* __restrict__ encw,
               const float* __restrict__ qa,
               const float* __restrict__ v_attn,
               const float* __restrict__ b_ap,
               float* __restrict__ attn_out,
               fp16* __restrict__ ah,
               float* __restrict__ ctxdot)
{
    int b = blockIdx.x;
    int tid = threadIdx.x;
    extern __shared__ float sm[];
    float* buf = sm;
    float* qs  = sm + SEQ * HD;
    float* ap  = qs + 4 * HD;
    float* sc  = ap + TT * SEQ;
    __shared__ __align__(16) float vsh[HD];
    __shared__ float ew[SEQ];

    for (int i = tid; i < SEQ * HD / 8; i += 256) {
        int idx = i * 8;
        int s = idx >> 9, d = idx & 511;
        uint4 v = *(const uint4*)(encctx + ((size_t)b * SEQ + s) * 1024 + d);
        float2 f0 = __half22float2(*(__half2*)&v.x);
        float2 f1 = __half22float2(*(__half2*)&v.y);
        float2 f2 = __half22float2(*(__half2*)&v.z);
        float2 f3 = __half22float2(*(__half2*)&v.w);
        float* o = buf + s * HD + d;
        o[0] = f0.x; o[1] = f0.y; o[2] = f1.x; o[3] = f1.y;
        o[4] = f2.x; o[5] = f2.y; o[6] = f3.x; o[7] = f3.y;
    }
    for (int d = tid; d < HD; d += 256) vsh[d] = v_attn[d];
    if (tid < SEQ) ew[tid] = encw[(size_t)b * SEQ + tid];
    __syncthreads();

    int w = tid >> 5, lane = tid & 31;
    for (int tc = 0; tc < TT; tc += 4) {
        for (int i = tid; i < 4 * HD / 4; i += 256) {
            int t = i / (HD / 4), dd = i % (HD / 4);
            ((float4*)qs)[i] =
                ((const float4*)(qa + ((size_t)(tc + t) * BATCH + b) * 1024))[dd];
        }
        __syncthreads();

        for (int task = w; task < 4 * SEQ; task += 8) {
            int t = task / SEQ, s = task % SEQ;
            const float4* row4 = (const float4*)(buf + s * HD);
            const float4* q4p = (const float4*)(qs + t * HD);
            float acc = 0.f;
#pragma unroll
            for (int j = 0; j < 4; j++) {
                int d4 = lane + j * 32;
                float4 e4 = row4[d4];
                float4 q4 = q4p[d4];
                float4 v4 = *(const float4*)&vsh[d4 * 4];
                acc += tanh_fast(e4.x + q4.x) * v4.x;
                acc += tanh_fast(e4.y + q4.y) * v4.y;
                acc += tanh_fast(e4.z + q4.z) * v4.z;
                acc += tanh_fast(e4.w + q4.w) * v4.w;
            }
#pragma unroll
            for (int o = 16; o; o >>= 1) acc += __shfl_xor_sync(0xffffffffu, acc, o);
            if (lane == 0) sc[t * SEQ + s] = acc;
        }
        __syncthreads();

        if (w < 4) {
            float e = (lane < SEQ) ? __expf(sc[w * SEQ + lane]) : 0.f;
            float sum = e;
#pragma unroll
            for (int o = 16; o; o >>= 1) sum += __shfl_xor_sync(0xffffffffu, sum, o);
            if (lane < SEQ) {
                float a = __fdividef(e, sum);
                ap[(tc + w) * SEQ + lane] = a;
                attn_out[(size_t)b * TT * SEQ + (size_t)(tc + w) * SEQ + lane] = a;
            }
        }
        __syncthreads();
    }

    if (tid < TT) {
        float cd = 0.f;
#pragma unroll
        for (int s = 0; s < SEQ; s++) cd += ap[tid * SEQ + s] * ew[s];
        ctxdot[(size_t)tid * BATCH + b] = cd;
    }
    for (int i = tid; i < SEQ * HD / 8; i += 256) {
        int idx = i * 8;
        int s = idx >> 9, d = idx & 511;
        uint4 v = *(const uint4*)(encctx + ((size_t)b * SEQ + s) * 1024 + 512 + d);
        float2 f0 = __half22float2(*(__half2*)&v.x);
        float2 f1 = __half22float2(*(__half2*)&v.y);
        float2 f2 = __half22float2(*(__half2*)&v.z);
        float2 f3 = __half22float2(*(__half2*)&v.w);
        float* o = buf + s * HD + d;
        o[0] = f0.x; o[1] = f0.y; o[2] = f1.x; o[3] = f1.y;
        o[4] = f2.x; o[5] = f2.y; o[6] = f3.x; o[7] = f3.y;
    }
    __syncthreads();

    float bap0 = b_ap[tid], bap1 = b_ap[tid + 256];
    for (int t = 0; t < TT; t++) {
        float a0 = 0.f, a1 = 0.f;
        const float* apt = ap + t * SEQ;
#pragma unroll
        for (int s = 0; s < SEQ; s++) {
            float a = apt[s];
            a0 += a * buf[s * HD + tid];
            a1 += a * buf[s * HD + tid + 256];
        }
        const float* qrow = qa + ((size_t)t * BATCH + b) * 1024 + 512;
        size_t base = (size_t)t * BATCH * HD + (size_t)b * HD;
        ah[base + tid]       = __float2half(tanh_fast(qrow[tid] + a0 + bap0));
        ah[base + tid + 256] = __float2half(tanh_fast(qrow[tid + 256] + a1 + bap1));
    }
}

// ---------------- output mix: warp per (t,b) row ----------------
__global__ void out2_k(const float* __restrict__ logits_all,
                       const float* __restrict__ ctxdot,
                       const int* __restrict__ input_char_ids,
                       const float* __restrict__ attn_base,
                       float* __restrict__ outputs)
{
    int warp = threadIdx.x >> 5, lane = threadIdx.x & 31;
    int row = blockIdx.x * 4 + warp;
    int t = row >> 12;
    int b = row & 4095;
    __shared__ float cbuf[4][VOC];

    for (int k = lane; k < VOC; k += 32) cbuf[warp][k] = 0.f;
    __syncwarp();
    if (lane < SEQ) {
        int id = input_char_ids[(size_t)b * SEQ + lane];
        float a = attn_base[(size_t)b * TT * SEQ + (size_t)t * SEQ + lane];
        atomicAdd(&cbuf[warp][id], a);
    }
    __syncwarp();

    const float* lrow = logits_all + (size_t)row * 121;
    float p = sigmoid_fast(lrow[120] + ctxdot[row]);

    float e[4];
    float sum = 0.f;
#pragma unroll
    for (int j = 0; j < 4; j++) {
        int idx = lane + j * 32;
        e[j] = (idx < VOC) ? __expf(lrow[idx]) : 0.f;
        sum += e[j];
    }
#pragma unroll
    for (int o = 16; o; o >>= 1) sum += __shfl_xor_sync(0xffffffffu, sum, o);
    float inv = __fdividef(1.0f - p, sum);
#pragma unroll
    for (int j = 0; j < 4; j++) {
        int idx = lane + j * 32;
        if (idx < VOC)
            outputs[(size_t)b * TT * VOC + (size_t)t * VOC + idx] =
                inv * e[j] + p * cbuf[warp][idx];
    }
}

// ---------------- host ----------------
#define SYM(p, s) cudaGetSymbolAddress((void**)&(p), s)
#define SM128 73728   // (128+128)*144*2
#define SM64  55296   // (128+64)*144*2

extern "C" void kernel_launch(void* const* d_in, const int* in_sizes, int n_in,
                              void* d_out, int out_size)
{
    (void)in_sizes; (void)n_in; (void)out_size;
    const float* enc        = (const float*)d_in[0];
    const float* enc_final  = (const float*)d_in[1];
    const int*   tgt        = (const int*)d_in[2];
    const int*   input_ids  = (const int*)d_in[3];
    const float* embed      = (const float*)d_in[4];
    const float* W_init     = (const float*)d_in[5];
    const float* b_init     = (const float*)d_in[6];
    const float* W_ih       = (const float*)d_in[7];
    const float* W_hh       = (const float*)d_in[8];
    const float* b_ih       = (const float*)d_in[9];
    const float* b_hh       = (const float*)d_in[10];
    const float* W_enc_attn = (const float*)d_in[11];
    const float* W_dec_attn = (const float*)d_in[12];
    const float* b_attn     = (const float*)d_in[13];
    const float* v_attn     = (const float*)d_in[14];
    const float* W_ap       = (const float*)d_in[15];
    const float* b_ap       = (const float*)d_in[16];
    const float* W_out      = (const float*)d_in[17];
    const float* b_out      = (const float*)d_in[18];
    const float* w_copy     = (const float*)d_in[19];
    const float* b_copy     = (const float*)d_in[20];

    float* out = (float*)d_out;
    float* outputs   = out;
    float* attn_base = out + (size_t)BATCH * TT * VOC;

    fp16 *ench, *ef, *encctx, *wg, *wqa, *wec, *woc, *wi, *h_all, *ah_all;
    float *encw, *embproj, *bqa, *boc, *cst;
    float *qa, *logits_all, *ctxdot;
    SYM(ench, g_ench); SYM(ef, g_ef);
    SYM(encctx, g_encctx); SYM(encw, g_encw);
    SYM(embproj, g_embproj);
    SYM(wg, g_wg);     SYM(wqa, g_wqa); SYM(bqa, g_bqa);
    SYM(wec, g_wec);
    SYM(woc, g_woc);   SYM(boc, g_boc);
    SYM(wi, g_wi);
    SYM(h_all, g_h_all);
    SYM(cst, g_c);     SYM(qa, g_qa);
    SYM(ah_all, g_ah_all);
    SYM(logits_all, g_logits_all); SYM(ctxdot, g_ctxdot);

    // one-time stream/event setup (no device memory allocation)
    static cudaStream_t s2 = nullptr;
    static cudaEvent_t evFork = nullptr, evJoin = nullptr;
    static bool inited = false;
    if (!inited) {
        cudaStreamCreateWithFlags(&s2, cudaStreamNonBlocking);
        cudaEventCreateWithFlags(&evFork, cudaEventDisableTiming);
        cudaEventCreateWithFlags(&evJoin, cudaEventDisableTiming);
        cudaFuncSetAttribute(mma_gemm_k<128, false>,
                             cudaFuncAttributeMaxDynamicSharedMemorySize, SM128);
        cudaFuncSetAttribute(mma_gemm_k<128, true>,
                             cudaFuncAttributeMaxDynamicSharedMemorySize, SM128);
        cudaFuncSetAttribute(mma_gemm_k<64, true>,
                             cudaFuncAttributeMaxDynamicSharedMemorySize, SM64);
        cudaFuncSetAttribute(comb_cell_k,
                             cudaFuncAttributeMaxDynamicSharedMemorySize, SM64);
        cudaFuncSetAttribute(attnctx_k,
                             cudaFuncAttributeMaxDynamicSharedMemorySize, AC_SMEM);
        inited = true;
    }

    // ---- prep on main (legacy) stream ----
    conv_h8_k<<<1024, 256>>>(enc_final, ef, (size_t)BATCH * HE / 8);
    embproj_k<<<dim3(16, VOC), 128>>>(embed, W_ih, b_ih, b_hh, embproj);
    prep_all_k<<<1024, 256>>>(W_hh, W_dec_attn, W_ap, b_attn, W_enc_attn,
                              W_out, b_out, w_copy, b_copy, W_init,
                              wg, wqa, bqa, wec, woc, boc, wi, cst);

    // ---- fork encoder-side chain onto s2 ----
    cudaEventRecord(evFork, 0);
    cudaStreamWaitEvent(s2, evFork, 0);
    conv_h8_k<<<2048, 256, 0, s2>>>(enc, ench, (size_t)BATCH * SEQ * HE / 8);
    encw_k<<<296, 256, 0, s2>>>(enc, w_copy, encw);
    // encctx = enc @ [W_enc^T ; W_ap2]^T  (N=1024, fp16 out)
    mma_gemm_k<128, true><<<dim3(8, 768), 256, SM128, s2>>>(
        ench, HE, wec, HE, nullptr,
        nullptr, encctx, HE, 1024);
    cudaEventRecord(evJoin, s2);

    // ---- main stream: h0 then the serial recurrence ----
    mma_gemm_k<64, true><<<dim3(8, 32), 256, SM64>>>(
        ef, HE, wi, HE, b_init,
        nullptr, h_all, HE, HD);
    for (int t = 0; t < TT; t++) {
        size_t off = (size_t)t * BATCH * HD;
        comb_cell_k<<<dim3(32, 32), 256, SM64>>>(
            h_all + off, wg, embproj, tgt,
            cst, h_all + off + (size_t)BATCH * HD, t);
    }

    // deferred: [q | ahp2] for ALL steps: M = T*B, N = 1024, K = 512
    mma_gemm_k<128, false><<<dim3(8, (TT * BATCH) / 128), 256, SM128>>>(
        h_all + (size_t)BATCH * HD, HD, wqa, HD, bqa,
        qa, nullptr, HD, 1024);

    // join encoder chain before attention consumes it
    cudaStreamWaitEvent(0, evJoin, 0);

    // merged attention + ctx + ah finalize + ctxdot
    attnctx_k<<<BATCH, 256, AC_SMEM>>>(
        encctx, encw, qa, v_attn, b_ap, attn_base, ah_all, ctxdot);

    // deferred logits+copy GEMM: M = T*B, N = 121, K = 512
    mma_gemm_k<128, false><<<dim3(1, (TT * BATCH) / 128), 256, SM128>>>(
        ah_all, HD, woc, HD, boc,
        logits_all, nullptr, HD, 121);
    out2_k<<<TT * BATCH / 4, 128>>>(logits_all, ctxdot, input_ids, attn_base, outputs);
}